// round 3
// baseline (speedup 1.0000x reference)
#include <cuda_runtime.h>
#include <math.h>

#define BB 256
#define TT 512
#define II 512
#define HH 512

typedef unsigned long long u64;

// Persistent scratch (__device__ globals: no runtime allocation)
__device__ float g_h[BB * HH];                   // hidden state
__device__ float g_u[BB * HH];                   // update gate
__device__ float g_rh[BB * HH];                  // reset * h
__device__ float g_p1[2 * BB * 1024];            // gates split-K partials
__device__ float g_p2[4 * BB * HH];              // cand split-K partials
__device__ unsigned g_bar[4 * TT];               // one counter per barrier event
__device__ float g_hist[(size_t)TT * BB * HH];   // h history [t][b][h]

// ---- packed f32x2 helpers (FFMA2: 2x fp32 throughput on sm_10x) ----
__device__ __forceinline__ u64 dup2(float v) {
    u64 r; asm("mov.b64 %0,{%1,%1};" : "=l"(r) : "f"(v)); return r;
}
__device__ __forceinline__ void fma2(u64& d, u64 a, u64 b) {
    asm("fma.rn.f32x2 %0,%1,%2,%0;" : "+l"(d) : "l"(a), "l"(b));
}
__device__ __forceinline__ float2 upk(u64 v) {
    float2 r; asm("mov.b64 {%0,%1},%2;" : "=f"(r.x), "=f"(r.y) : "l"(v)); return r;
}
__device__ __forceinline__ float sigm(float v) { return 1.0f / (1.0f + expf(-v)); }

// Software grid barrier: per-event counter (zeroed by k_init each replay).
__device__ __forceinline__ void gridbar(int idx, int nCTA) {
    __syncthreads();
    if (threadIdx.x == 0) {
        __threadfence();
        atomicAdd(&g_bar[idx], 1u);
        while (*(volatile unsigned*)&g_bar[idx] < (unsigned)nCTA) { __nanosleep(32); }
        __threadfence();
    }
    __syncthreads();
}

// ============================================================================
// Persistent kernel: all 512 recurrence steps.
// GEMM tiles: [64x64], BK=32, 256 threads, thread tile 4x4 (8 f32x2 accs).
// ============================================================================
__global__ __launch_bounds__(256, 1) void k_persist(
    const float* __restrict__ x,
    const float* __restrict__ Wg, const float* __restrict__ bg,
    const float* __restrict__ Wh, const float* __restrict__ bh,
    int nCTA)
{
    __shared__ __align__(16) float Asd[32][132];  // A duplicated: [k][2*m (+pad)]
    __shared__ __align__(16) float Bs[32][64];

    const int tid = threadIdx.x;
    // A loader: 64 rows x 32 cols, 8 floats/thread (2 float4 along k)
    const int arow = tid >> 2;
    const int acg  = (tid & 3) * 8;
    // B loader: 32 rows x 64 cols, 8 floats/thread (2 float4 along n)
    const int bk   = tid >> 3;
    const int bng  = (tid & 7) * 8;
    // compute: thread (rr, cc) owns rows 4rr..4rr+3, cols 4cc..4cc+3
    const int rr = tid >> 4, cc = tid & 15;
    const int thr = nCTA * 256;

    for (int t = 0; t < TT; t++) {
        // ---------------- Phase 1: gates partial GEMM (128 jobs) -----------
        for (int j = blockIdx.x; j < 128; j += nCTA) {
            const int kk = j >> 6;                 // split-K half: 0=x, 1=h
            const int tile = j & 63;
            const int m0 = (tile >> 4) * 64;
            const int n0 = (tile & 15) * 64;

            const float* Ab;
            const bool a_is_x = (kk == 0);
            if (a_is_x) Ab = x + (size_t)(m0 + arow) * (TT * II) + (size_t)t * II + acg;
            else        Ab = g_h + (size_t)(m0 + arow) * HH + acg;
            const float* Bb = Wg + (size_t)(kk * 512 + bk) * 1024 + n0 + bng;

            float4 ra0, ra1, rb0, rb1;
            if (a_is_x) { ra0 = __ldg((const float4*)Ab); ra1 = __ldg((const float4*)(Ab + 4)); }
            else        { ra0 = __ldcg((const float4*)Ab); ra1 = __ldcg((const float4*)(Ab + 4)); }
            rb0 = __ldg((const float4*)Bb); rb1 = __ldg((const float4*)(Bb + 4));

            u64 acc[8];
#pragma unroll
            for (int q = 0; q < 8; q++) acc[q] = 0ull;

            for (int blk = 0; blk < 16; blk++) {
                const float af[8] = {ra0.x, ra0.y, ra0.z, ra0.w, ra1.x, ra1.y, ra1.z, ra1.w};
#pragma unroll
                for (int i = 0; i < 8; i++) *(u64*)&Asd[acg + i][2 * arow] = dup2(af[i]);
                *(float4*)&Bs[bk][bng]     = rb0;
                *(float4*)&Bs[bk][bng + 4] = rb1;
                __syncthreads();

                if (blk < 15) {
                    const float* An = Ab + (blk + 1) * 32;
                    if (a_is_x) { ra0 = __ldg((const float4*)An); ra1 = __ldg((const float4*)(An + 4)); }
                    else        { ra0 = __ldcg((const float4*)An); ra1 = __ldcg((const float4*)(An + 4)); }
                    const float* Bn = Bb + (size_t)(blk + 1) * 32 * 1024;
                    rb0 = __ldg((const float4*)Bn); rb1 = __ldg((const float4*)(Bn + 4));
                }

#pragma unroll
                for (int k = 0; k < 32; k++) {
                    ulonglong2 a01 = *(const ulonglong2*)&Asd[k][8 * rr];
                    ulonglong2 a23 = *(const ulonglong2*)&Asd[k][8 * rr + 4];
                    ulonglong2 bv  = *(const ulonglong2*)&Bs[k][4 * cc];
                    fma2(acc[0], a01.x, bv.x); fma2(acc[1], a01.x, bv.y);
                    fma2(acc[2], a01.y, bv.x); fma2(acc[3], a01.y, bv.y);
                    fma2(acc[4], a23.x, bv.x); fma2(acc[5], a23.x, bv.y);
                    fma2(acc[6], a23.y, bv.x); fma2(acc[7], a23.y, bv.y);
                }
                __syncthreads();
            }

            float* P = g_p1 + (size_t)kk * (BB * 1024);
#pragma unroll
            for (int r = 0; r < 4; r++) {
                const size_t row = (size_t)(m0 + 4 * rr + r) * 1024 + n0 + 4 * cc;
                __stcg((float2*)&P[row],     *(float2*)&acc[2 * r]);
                __stcg((float2*)&P[row + 2], *(float2*)&acc[2 * r + 1]);
            }
        }
        gridbar(4 * t + 0, nCTA);

        // ---------------- act1: reduce + sigmoid -> u, r*h ------------------
        for (int i = blockIdx.x * 256 + tid; i < BB * 1024; i += thr) {
            const int n = i & 1023;
            float v = __ldcg(&g_p1[i]) + __ldcg(&g_p1[i + BB * 1024]) + __ldg(&bg[n]);
            v = sigm(v);
            const int b = i >> 10;
            if (n < HH) {
                __stcg(&g_u[b * HH + n], v);
            } else {
                const int nn = n - HH;
                __stcg(&g_rh[b * HH + nn], v * __ldcg(&g_h[b * HH + nn]));
            }
        }
        gridbar(4 * t + 1, nCTA);

        // ---------------- Phase 2: cand partial GEMM (128 jobs) -------------
        for (int j = blockIdx.x; j < 128; j += nCTA) {
            const int kk = j >> 5;                 // split-K quarter: 0,1=x  2,3=rh
            const int tile = j & 31;
            const int m0 = (tile >> 3) * 64;
            const int n0 = (tile & 7) * 64;
            const int kbase = kk * 256;

            const float* Ab;
            const bool a_is_x = (kk < 2);
            if (a_is_x) Ab = x + (size_t)(m0 + arow) * (TT * II) + (size_t)t * II + kbase + acg;
            else        Ab = g_rh + (size_t)(m0 + arow) * HH + (kbase - 512) + acg;
            const float* Bb = Wh + (size_t)(kbase + bk) * HH + n0 + bng;

            float4 ra0, ra1, rb0, rb1;
            if (a_is_x) { ra0 = __ldg((const float4*)Ab); ra1 = __ldg((const float4*)(Ab + 4)); }
            else        { ra0 = __ldcg((const float4*)Ab); ra1 = __ldcg((const float4*)(Ab + 4)); }
            rb0 = __ldg((const float4*)Bb); rb1 = __ldg((const float4*)(Bb + 4));

            u64 acc[8];
#pragma unroll
            for (int q = 0; q < 8; q++) acc[q] = 0ull;

            for (int blk = 0; blk < 8; blk++) {
                const float af[8] = {ra0.x, ra0.y, ra0.z, ra0.w, ra1.x, ra1.y, ra1.z, ra1.w};
#pragma unroll
                for (int i = 0; i < 8; i++) *(u64*)&Asd[acg + i][2 * arow] = dup2(af[i]);
                *(float4*)&Bs[bk][bng]     = rb0;
                *(float4*)&Bs[bk][bng + 4] = rb1;
                __syncthreads();

                if (blk < 7) {
                    const float* An = Ab + (blk + 1) * 32;
                    if (a_is_x) { ra0 = __ldg((const float4*)An); ra1 = __ldg((const float4*)(An + 4)); }
                    else        { ra0 = __ldcg((const float4*)An); ra1 = __ldcg((const float4*)(An + 4)); }
                    const float* Bn = Bb + (size_t)(blk + 1) * 32 * HH;
                    rb0 = __ldg((const float4*)Bn); rb1 = __ldg((const float4*)(Bn + 4));
                }

#pragma unroll
                for (int k = 0; k < 32; k++) {
                    ulonglong2 a01 = *(const ulonglong2*)&Asd[k][8 * rr];
                    ulonglong2 a23 = *(const ulonglong2*)&Asd[k][8 * rr + 4];
                    ulonglong2 bv  = *(const ulonglong2*)&Bs[k][4 * cc];
                    fma2(acc[0], a01.x, bv.x); fma2(acc[1], a01.x, bv.y);
                    fma2(acc[2], a01.y, bv.x); fma2(acc[3], a01.y, bv.y);
                    fma2(acc[4], a23.x, bv.x); fma2(acc[5], a23.x, bv.y);
                    fma2(acc[6], a23.y, bv.x); fma2(acc[7], a23.y, bv.y);
                }
                __syncthreads();
            }

            float* P = g_p2 + (size_t)kk * (BB * HH);
#pragma unroll
            for (int r = 0; r < 4; r++) {
                const size_t row = (size_t)(m0 + 4 * rr + r) * HH + n0 + 4 * cc;
                __stcg((float2*)&P[row],     *(float2*)&acc[2 * r]);
                __stcg((float2*)&P[row + 2], *(float2*)&acc[2 * r + 1]);
            }
        }
        gridbar(4 * t + 2, nCTA);

        // ---------------- act2: reduce + tanh + h update + history ----------
        for (int i = blockIdx.x * 256 + tid; i < BB * HH; i += thr) {
            float s = __ldcg(&g_p2[i]) + __ldcg(&g_p2[i + BB * HH]) +
                      __ldcg(&g_p2[i + 2 * BB * HH]) + __ldcg(&g_p2[i + 3 * BB * HH]) +
                      __ldg(&bh[i & 511]);
            const float cand = tanhf(s);
            const float u = __ldcg(&g_u[i]);
            const float h = __ldcg(&g_h[i]);
            const float hn = fmaf(u, cand - h, h);     // (1-u)h + u*cand
            __stcg(&g_h[i], hn);
            g_hist[(size_t)t * (BB * HH) + i] = hn;
        }
        gridbar(4 * t + 3, nCTA);
    }
}

// ============================================================================
// k_y: output head off the critical path.
//   Z = g_hist[131072,512] @ Wo1[512,256] + bo1; y = relu(Z) @ Wo2 + bo2
// ============================================================================
__global__ __launch_bounds__(256) void k_y(
    const float* __restrict__ Wo1, const float* __restrict__ bo1,
    const float* __restrict__ Wo2, const float* __restrict__ bo2,
    float* __restrict__ out)
{
    __shared__ __align__(16) float Asd[32][68];
    __shared__ __align__(16) float Bs[32][256];

    const int tid = threadIdx.x;
    const long m0 = (long)blockIdx.x * 32;
    const int lk = tid & 31, lm = tid >> 5;
    const int rg = tid >> 5, cg = tid & 31;

    u64 acc[4][4];
#pragma unroll
    for (int r = 0; r < 4; r++)
#pragma unroll
        for (int p = 0; p < 4; p++) acc[r][p] = 0ull;

    for (int k0 = 0; k0 < HH; k0 += 32) {
        const float* ap = g_hist + m0 * HH + k0 + lk;
#pragma unroll
        for (int i = 0; i < 4; i++) {
            float v = ap[(long)(lm + 8 * i) * HH];
            *(u64*)&Asd[lk][2 * (lm + 8 * i)] = dup2(v);
        }
        const int bn = (tid & 63) * 4;
        const int bkk = tid >> 6;
#pragma unroll
        for (int j = 0; j < 8; j++) {
            float4 v = *(const float4*)&Wo1[(long)(k0 + bkk + 4 * j) * 256 + bn];
            *(float4*)&Bs[bkk + 4 * j][bn] = v;
        }
        __syncthreads();

#pragma unroll
        for (int k = 0; k < 32; k++) {
            ulonglong2 a01 = *(const ulonglong2*)&Asd[k][8 * rg];
            ulonglong2 a23 = *(const ulonglong2*)&Asd[k][8 * rg + 4];
            ulonglong2 b01 = *(const ulonglong2*)&Bs[k][8 * cg];
            ulonglong2 b23 = *(const ulonglong2*)&Bs[k][8 * cg + 4];
            fma2(acc[0][0], a01.x, b01.x); fma2(acc[0][1], a01.x, b01.y);
            fma2(acc[0][2], a01.x, b23.x); fma2(acc[0][3], a01.x, b23.y);
            fma2(acc[1][0], a01.y, b01.x); fma2(acc[1][1], a01.y, b01.y);
            fma2(acc[1][2], a01.y, b23.x); fma2(acc[1][3], a01.y, b23.y);
            fma2(acc[2][0], a23.x, b01.x); fma2(acc[2][1], a23.x, b01.y);
            fma2(acc[2][2], a23.x, b23.x); fma2(acc[2][3], a23.x, b23.y);
            fma2(acc[3][0], a23.y, b01.x); fma2(acc[3][1], a23.y, b01.y);
            fma2(acc[3][2], a23.y, b23.x); fma2(acc[3][3], a23.y, b23.y);
        }
        __syncthreads();
    }

    float b1[8], w2[8];
#pragma unroll
    for (int q = 0; q < 8; q++) { const int n = 8 * cg + q; b1[q] = bo1[n]; w2[q] = Wo2[n]; }
    const float bo2v = bo2[0];

#pragma unroll
    for (int r = 0; r < 4; r++) {
        float part = 0.f;
#pragma unroll
        for (int p = 0; p < 4; p++) {
            float2 z = upk(acc[r][p]);
            float z0 = fmaxf(z.x + b1[2 * p], 0.f);
            float z1 = fmaxf(z.y + b1[2 * p + 1], 0.f);
            part = fmaf(z0, w2[2 * p], part);
            part = fmaf(z1, w2[2 * p + 1], part);
        }
#pragma unroll
        for (int o = 16; o > 0; o >>= 1) part += __shfl_xor_sync(0xffffffffu, part, o);
        if (cg == 0) {
            const long m = m0 + 4 * rg + r;       // m = t*256 + b
            const int b = (int)(m & 255);
            const int tt = (int)(m >> 8);
            out[(long)b * TT + tt] = part + bo2v; // ys[b][t][0]
        }
    }
}

__global__ void k_init() {
    const int i = blockIdx.x * 256 + threadIdx.x;
    if (i < BB * HH) g_h[i] = 0.f;
    if (i < 4 * TT) g_bar[i] = 0u;
}

__global__ void k_hfinal(float* __restrict__ out) {
    const int i = blockIdx.x * 256 + threadIdx.x;
    out[(long)BB * TT + i] = g_h[i];
}

// ============================================================================
extern "C" void kernel_launch(void* const* d_in, const int* in_sizes, int n_in,
                              void* d_out, int out_size)
{
    (void)in_sizes; (void)n_in;
    const float* x   = (const float*)d_in[0];
    const float* Wg  = (const float*)d_in[1];
    const float* bg  = (const float*)d_in[2];
    const float* Wh  = (const float*)d_in[3];
    const float* bh  = (const float*)d_in[4];
    const float* Wo1 = (const float*)d_in[5];
    const float* bo1 = (const float*)d_in[6];
    const float* Wo2 = (const float*)d_in[7];
    const float* bo2 = (const float*)d_in[8];
    float* out = (float*)d_out;

    int dev = 0, nsm = 0;
    cudaGetDevice(&dev);
    cudaDeviceGetAttribute(&nsm, cudaDevAttrMultiProcessorCount, dev);
    if (nsm <= 0) nsm = 148;

    k_init<<<512, 256>>>();
    k_persist<<<nsm, 256>>>(x, Wg, bg, Wh, bh, nsm);
    k_y<<<(BB * TT) / 32, 256>>>(Wo1, bo1, Wo2, bo2, out);

    if (out_size >= BB * TT + BB * HH)
        k_hfinal<<<(BB * HH) / 256, 256>>>(out);
}

// round 4
// speedup vs baseline: 1.1584x; 1.1584x over previous
#include <cuda_runtime.h>
#include <math.h>

#define BB 256
#define TT 512
#define II 512
#define HH 512

typedef unsigned long long u64;

// ---------------- persistent __device__ scratch (no runtime allocation) ----
__device__ float g_h[BB * HH];                    // hidden state
__device__ float g_u[BB * HH];                    // update gate
__device__ float g_rh[BB * HH];                   // reset * h
__device__ unsigned g_bar[2 * TT];                // grid-barrier counters
__device__ float g_gx[(size_t)TT * BB * 1024];    // x@Wg_x + bg   [t][b][1024] (512 MB)
__device__ float g_cx[(size_t)TT * BB * HH];      // x@Wh_x + bh   [t][b][512]  (256 MB)
__device__ float g_hist[(size_t)TT * BB * HH];    // h history     [t][b][512]  (256 MB)

// ---- packed f32x2 helpers (FFMA2: 2x fp32 throughput) ----
__device__ __forceinline__ u64 dup2(float v) {
    u64 r; asm("mov.b64 %0,{%1,%1};" : "=l"(r) : "f"(v)); return r;
}
__device__ __forceinline__ void fma2(u64& d, u64 a, u64 b) {
    asm("fma.rn.f32x2 %0,%1,%2,%0;" : "+l"(d) : "l"(a), "l"(b));
}
__device__ __forceinline__ float2 upk(u64 v) {
    float2 r; asm("mov.b64 {%0,%1},%2;" : "=f"(r.x), "=f"(r.y) : "l"(v)); return r;
}
__device__ __forceinline__ float sigm(float v) { return 1.0f / (1.0f + expf(-v)); }

__device__ __forceinline__ void gridbar(int idx, int nCTA) {
    __syncthreads();
    if (threadIdx.x == 0) {
        __threadfence();
        atomicAdd(&g_bar[idx], 1u);
        while (*(volatile unsigned*)&g_bar[idx] < (unsigned)nCTA) { __nanosleep(32); }
        __threadfence();
    }
    __syncthreads();
}

// ============================================================================
// k_pre: bulk x-projection (off the critical path).
//   C[131072,1536] = x[131072,512] @ [Wg_x | Wh_x] (+bias), scattered to gx/cx.
// 64x64 tiles, BK=32, 256 threads, thread tile 4x4 (8 f32x2 accs).
// ============================================================================
__global__ __launch_bounds__(256) void k_pre(
    const float* __restrict__ x,
    const float* __restrict__ Wg, const float* __restrict__ bg,
    const float* __restrict__ Wh, const float* __restrict__ bh)
{
    __shared__ __align__(16) float Asd[32][132];
    __shared__ __align__(16) float Bs[32][64];

    const int tid = threadIdx.x;
    const int bid = blockIdx.x;
    const int nt = bid % 24;                       // n-tile (0..15 Wg, 16..23 Wh)
    const long m0 = (long)(bid / 24) * 64;

    const float* Bp; long ldb; int gcol0;
    if (nt < 16) { Bp = Wg + nt * 64;        ldb = 1024; gcol0 = nt * 64; }
    else         { Bp = Wh + (nt - 16) * 64; ldb = 512;  gcol0 = 1024 + (nt - 16) * 64; }

    const int arow = tid >> 2, acg = (tid & 3) * 8;   // A: 64 rows x 32 k
    const int bkr = tid >> 3, bcg = (tid & 7) * 8;    // B: 32 k x 64 n
    const int rr = tid >> 4, cc = tid & 15;           // compute: 4 rows, 4 cols

    u64 acc[4][2];
#pragma unroll
    for (int r = 0; r < 4; r++) { acc[r][0] = 0ull; acc[r][1] = 0ull; }

    const float* Ab = x + (m0 + arow) * II + acg;
    float4 ra0 = __ldg((const float4*)Ab), ra1 = __ldg((const float4*)(Ab + 4));
    const float* Bb = Bp + (long)bkr * ldb + bcg;
    float4 rb0 = __ldg((const float4*)Bb), rb1 = __ldg((const float4*)(Bb + 4));

    for (int kb = 0; kb < 16; kb++) {
        {
            const float af[8] = {ra0.x, ra0.y, ra0.z, ra0.w, ra1.x, ra1.y, ra1.z, ra1.w};
#pragma unroll
            for (int i = 0; i < 8; i++) *(u64*)&Asd[acg + i][2 * arow] = dup2(af[i]);
        }
        *(float4*)&Bs[bkr][bcg] = rb0;
        *(float4*)&Bs[bkr][bcg + 4] = rb1;
        __syncthreads();

        if (kb < 15) {
            const float* An = Ab + (kb + 1) * 32;
            ra0 = __ldg((const float4*)An); ra1 = __ldg((const float4*)(An + 4));
            const float* Bn = Bb + (long)(kb + 1) * 32 * ldb;
            rb0 = __ldg((const float4*)Bn); rb1 = __ldg((const float4*)(Bn + 4));
        }

#pragma unroll
        for (int k = 0; k < 32; k++) {
            ulonglong2 a01 = *(const ulonglong2*)&Asd[k][8 * rr];
            ulonglong2 a23 = *(const ulonglong2*)&Asd[k][8 * rr + 4];
            ulonglong2 bv  = *(const ulonglong2*)&Bs[k][4 * cc];
            fma2(acc[0][0], a01.x, bv.x); fma2(acc[0][1], a01.x, bv.y);
            fma2(acc[1][0], a01.y, bv.x); fma2(acc[1][1], a01.y, bv.y);
            fma2(acc[2][0], a23.x, bv.x); fma2(acc[2][1], a23.x, bv.y);
            fma2(acc[3][0], a23.y, bv.x); fma2(acc[3][1], a23.y, bv.y);
        }
        __syncthreads();
    }

    const int gcol = gcol0 + 4 * cc;
    float4 bias;
    if (gcol0 < 1024) bias = *(const float4*)&bg[gcol];
    else              bias = *(const float4*)&bh[gcol - 1024];

#pragma unroll
    for (int r = 0; r < 4; r++) {
        const long row = m0 + 4 * rr + r;          // row = b*512 + t
        const long b = row >> 9, t = row & 511;
        float2 c0 = upk(acc[r][0]), c1 = upk(acc[r][1]);
        float4 v = make_float4(c0.x + bias.x, c0.y + bias.y, c1.x + bias.z, c1.y + bias.w);
        if (gcol0 < 1024) *(float4*)&g_gx[(t * BB + b) * 1024 + gcol] = v;
        else              *(float4*)&g_cx[(t * BB + b) * 512 + (gcol - 1024)] = v;
    }
}

// ============================================================================
// k_persist: 512 recurrence steps. 128 CTAs, weights resident in SMEM.
//  Phase1: gates_h = h @ Wg_h  (tile 64x32, K=512)  -> sigmoid -> u / rh
//  Phase2: cand    = rh @ Wh_h (tile 32x32, K=512)  -> tanh -> h update
// Dynamic smem: B1[512][32] | B2[512][32] | Asd[32][132]
// ============================================================================
#define NCTA 128
#define SM_B1 0
#define SM_B2 16384
#define SM_AS 32768
#define AS_LD 132
#define SMEM_FLOATS (32768 + 32 * AS_LD)

__global__ __launch_bounds__(256, 1) void k_persist(
    const float* __restrict__ Wg, const float* __restrict__ Wh)
{
    extern __shared__ __align__(16) float sm[];
    float* B1s = sm + SM_B1;
    float* B2s = sm + SM_B2;
    float* Asd = sm + SM_AS;

    const int tid = threadIdx.x;
    const int c = blockIdx.x;

    // ----- phase-1 tile: m0 (64 rows), n0 (32 of 1024 gate cols) -----
    const int m0 = (c >> 5) * 64;
    const int n0 = (c & 31) * 32;
    // ----- phase-2 tile: m0b (32 rows), n0b (32 of 512 cols) -----
    const int m0b = (c >> 4) * 32;
    const int n0b = (c & 15) * 32;

    // ----- load resident weight slices (once) -----
    // B1: Wg rows 512..1023, cols n0..n0+31 ; B2: Wh rows 512..1023, cols n0b..+31
    {
        const int r0 = tid >> 3, c4 = (tid & 7) * 4;  // 32 rows/pass x 8 col-groups
        for (int rep = 0; rep < 16; rep++) {
            const int krow = rep * 32 + r0;
            *(float4*)&B1s[krow * 32 + c4] = __ldg((const float4*)&Wg[(size_t)(512 + krow) * 1024 + n0 + c4]);
            *(float4*)&B2s[krow * 32 + c4] = __ldg((const float4*)&Wh[(size_t)(512 + krow) * 512 + n0b + c4]);
        }
    }
    __syncthreads();

    // loader/compute index sets
    const int arow = tid >> 2, acg = (tid & 3) * 8;    // phase1 A: 64 rows x 32 k
    const int rr1 = tid >> 3, cc1 = tid & 7;           // phase1: 2 rows x 4 cols
    const int arow2 = tid >> 3, acg2 = (tid & 7) * 4;  // phase2 A: 32 rows x 32 k
    const int rr2 = tid >> 4, cc2 = tid & 15;          // phase2: 2 rows x 2 cols

    for (int t = 0; t < TT; t++) {
        // =================== Phase 1: h @ Wg_h ===================
        {
            // epilogue operand prefetch (hidden under the k-loop)
            const int b0 = m0 + 2 * rr1, nn = n0 + 4 * cc1;
            const size_t gxo = ((size_t)t * BB + b0) * 1024 + nn;
            float4 gx0 = __ldg((const float4*)&g_gx[gxo]);
            float4 gx1 = __ldg((const float4*)&g_gx[gxo + 1024]);
            float4 h0, h1;
            if (n0 >= 512) {
                h0 = __ldcg((const float4*)&g_h[(size_t)b0 * 512 + (nn - 512)]);
                h1 = __ldcg((const float4*)&g_h[(size_t)(b0 + 1) * 512 + (nn - 512)]);
            }

            u64 a00 = 0, a01v = 0, a10 = 0, a11 = 0;
            const float* Ab = g_h + (size_t)(m0 + arow) * 512 + acg;
            float4 ra0 = __ldcg((const float4*)Ab), ra1 = __ldcg((const float4*)(Ab + 4));

            for (int kb = 0; kb < 16; kb++) {
                {
                    const float af[8] = {ra0.x, ra0.y, ra0.z, ra0.w, ra1.x, ra1.y, ra1.z, ra1.w};
#pragma unroll
                    for (int i = 0; i < 8; i++) *(u64*)&Asd[(acg + i) * AS_LD + 2 * arow] = dup2(af[i]);
                }
                __syncthreads();
                if (kb < 15) {
                    const float* An = Ab + (kb + 1) * 32;
                    ra0 = __ldcg((const float4*)An); ra1 = __ldcg((const float4*)(An + 4));
                }
                const float* Bk = B1s + kb * 32 * 32;
#pragma unroll
                for (int k = 0; k < 32; k++) {
                    ulonglong2 a = *(const ulonglong2*)&Asd[k * AS_LD + 4 * rr1];
                    ulonglong2 b = *(const ulonglong2*)&Bk[k * 32 + 4 * cc1];
                    fma2(a00, a.x, b.x); fma2(a01v, a.x, b.y);
                    fma2(a10, a.y, b.x); fma2(a11, a.y, b.y);
                }
                __syncthreads();
            }

            float2 p00 = upk(a00), p01 = upk(a01v), p10 = upk(a10), p11 = upk(a11);
            float4 v0 = make_float4(sigm(p00.x + gx0.x), sigm(p00.y + gx0.y),
                                    sigm(p01.x + gx0.z), sigm(p01.y + gx0.w));
            float4 v1 = make_float4(sigm(p10.x + gx1.x), sigm(p10.y + gx1.y),
                                    sigm(p11.x + gx1.z), sigm(p11.y + gx1.w));
            if (n0 < 512) {
                __stcg((float4*)&g_u[(size_t)b0 * 512 + nn], v0);
                __stcg((float4*)&g_u[(size_t)(b0 + 1) * 512 + nn], v1);
            } else {
                float4 r0 = make_float4(v0.x * h0.x, v0.y * h0.y, v0.z * h0.z, v0.w * h0.w);
                float4 r1 = make_float4(v1.x * h1.x, v1.y * h1.y, v1.z * h1.z, v1.w * h1.w);
                __stcg((float4*)&g_rh[(size_t)b0 * 512 + (nn - 512)], r0);
                __stcg((float4*)&g_rh[(size_t)(b0 + 1) * 512 + (nn - 512)], r1);
            }
        }
        gridbar(2 * t + 0, NCTA);

        // =================== Phase 2: rh @ Wh_h ===================
        {
            const int b0 = m0b + 2 * rr2, nn = n0b + 2 * cc2;
            const size_t cxo = ((size_t)t * BB + b0) * 512 + nn;
            float2 cx0 = __ldg((const float2*)&g_cx[cxo]);
            float2 cx1 = __ldg((const float2*)&g_cx[cxo + 512]);
            float2 u0 = __ldcg((const float2*)&g_u[(size_t)b0 * 512 + nn]);
            float2 u1 = __ldcg((const float2*)&g_u[(size_t)(b0 + 1) * 512 + nn]);
            float2 h0 = __ldcg((const float2*)&g_h[(size_t)b0 * 512 + nn]);
            float2 h1 = __ldcg((const float2*)&g_h[(size_t)(b0 + 1) * 512 + nn]);

            u64 a0 = 0, a1 = 0;
            const float* Ab = g_rh + (size_t)(m0b + arow2) * 512 + acg2;
            float4 ra = __ldcg((const float4*)Ab);

            for (int kb = 0; kb < 16; kb++) {
                {
                    const float af[4] = {ra.x, ra.y, ra.z, ra.w};
#pragma unroll
                    for (int i = 0; i < 4; i++) *(u64*)&Asd[(acg2 + i) * AS_LD + 2 * arow2] = dup2(af[i]);
                }
                __syncthreads();
                if (kb < 15) ra = __ldcg((const float4*)(Ab + (kb + 1) * 32));
                const float* Bk = B2s + kb * 32 * 32;
#pragma unroll
                for (int k = 0; k < 32; k++) {
                    ulonglong2 a = *(const ulonglong2*)&Asd[k * AS_LD + 4 * rr2];
                    u64 b = *(const u64*)&Bk[k * 32 + 2 * cc2];
                    fma2(a0, a.x, b); fma2(a1, a.y, b);
                }
                __syncthreads();
            }

            float2 p0 = upk(a0), p1 = upk(a1);
            float c00 = tanhf(p0.x + cx0.x), c01 = tanhf(p0.y + cx0.y);
            float c10 = tanhf(p1.x + cx1.x), c11 = tanhf(p1.y + cx1.y);
            float2 hn0 = make_float2(fmaf(u0.x, c00 - h0.x, h0.x), fmaf(u0.y, c01 - h0.y, h0.y));
            float2 hn1 = make_float2(fmaf(u1.x, c10 - h1.x, h1.x), fmaf(u1.y, c11 - h1.y, h1.y));
            __stcg((float2*)&g_h[(size_t)b0 * 512 + nn], hn0);
            __stcg((float2*)&g_h[(size_t)(b0 + 1) * 512 + nn], hn1);
            const size_t ho = ((size_t)t * BB + b0) * 512 + nn;
            *(float2*)&g_hist[ho] = hn0;
            *(float2*)&g_hist[ho + 512] = hn1;
        }
        gridbar(2 * t + 1, NCTA);
    }
}

// ============================================================================
// k_y: output head off the critical path.
//   Z = g_hist[131072,512] @ Wo1[512,256] + bo1; y = relu(Z) @ Wo2 + bo2
// ============================================================================
__global__ __launch_bounds__(256) void k_y(
    const float* __restrict__ Wo1, const float* __restrict__ bo1,
    const float* __restrict__ Wo2, const float* __restrict__ bo2,
    float* __restrict__ out)
{
    __shared__ __align__(16) float Asd[32][68];
    __shared__ __align__(16) float Bs[32][256];

    const int tid = threadIdx.x;
    const long m0 = (long)blockIdx.x * 32;
    const int lk = tid & 31, lm = tid >> 5;
    const int rg = tid >> 5, cg = tid & 31;

    u64 acc[4][4];
#pragma unroll
    for (int r = 0; r < 4; r++)
#pragma unroll
        for (int p = 0; p < 4; p++) acc[r][p] = 0ull;

    for (int k0 = 0; k0 < HH; k0 += 32) {
        const float* ap = g_hist + m0 * HH + k0 + lk;
#pragma unroll
        for (int i = 0; i < 4; i++) {
            float v = ap[(long)(lm + 8 * i) * HH];
            *(u64*)&Asd[lk][2 * (lm + 8 * i)] = dup2(v);
        }
        const int bn = (tid & 63) * 4;
        const int bkk = tid >> 6;
#pragma unroll
        for (int j = 0; j < 8; j++) {
            float4 v = *(const float4*)&Wo1[(long)(k0 + bkk + 4 * j) * 256 + bn];
            *(float4*)&Bs[bkk + 4 * j][bn] = v;
        }
        __syncthreads();

#pragma unroll
        for (int k = 0; k < 32; k++) {
            ulonglong2 a01 = *(const ulonglong2*)&Asd[k][8 * rg];
            ulonglong2 a23 = *(const ulonglong2*)&Asd[k][8 * rg + 4];
            ulonglong2 b01 = *(const ulonglong2*)&Bs[k][8 * cg];
            ulonglong2 b23 = *(const ulonglong2*)&Bs[k][8 * cg + 4];
            fma2(acc[0][0], a01.x, b01.x); fma2(acc[0][1], a01.x, b01.y);
            fma2(acc[0][2], a01.x, b23.x); fma2(acc[0][3], a01.x, b23.y);
            fma2(acc[1][0], a01.y, b01.x); fma2(acc[1][1], a01.y, b01.y);
            fma2(acc[1][2], a01.y, b23.x); fma2(acc[1][3], a01.y, b23.y);
            fma2(acc[2][0], a23.x, b01.x); fma2(acc[2][1], a23.x, b01.y);
            fma2(acc[2][2], a23.x, b23.x); fma2(acc[2][3], a23.x, b23.y);
            fma2(acc[3][0], a23.y, b01.x); fma2(acc[3][1], a23.y, b01.y);
            fma2(acc[3][2], a23.y, b23.x); fma2(acc[3][3], a23.y, b23.y);
        }
        __syncthreads();
    }

    float b1[8], w2[8];
#pragma unroll
    for (int q = 0; q < 8; q++) { const int n = 8 * cg + q; b1[q] = bo1[n]; w2[q] = Wo2[n]; }
    const float bo2v = bo2[0];

#pragma unroll
    for (int r = 0; r < 4; r++) {
        float part = 0.f;
#pragma unroll
        for (int p = 0; p < 4; p++) {
            float2 z = upk(acc[r][p]);
            float z0 = fmaxf(z.x + b1[2 * p], 0.f);
            float z1 = fmaxf(z.y + b1[2 * p + 1], 0.f);
            part = fmaf(z0, w2[2 * p], part);
            part = fmaf(z1, w2[2 * p + 1], part);
        }
#pragma unroll
        for (int o = 16; o > 0; o >>= 1) part += __shfl_xor_sync(0xffffffffu, part, o);
        if (cg == 0) {
            const long m = m0 + 4 * rg + r;       // m = t*256 + b
            const int b = (int)(m & 255);
            const int tt = (int)(m >> 8);
            out[(long)b * TT + tt] = part + bo2v; // ys[b][t][0]
        }
    }
}

__global__ void k_init() {
    const int i = blockIdx.x * 256 + threadIdx.x;
    if (i < BB * HH) g_h[i] = 0.f;
    if (i < 2 * TT) g_bar[i] = 0u;
}

__global__ void k_hfinal(float* __restrict__ out) {
    const int i = blockIdx.x * 256 + threadIdx.x;
    out[(long)BB * TT + i] = g_h[i];
}

// ============================================================================
extern "C" void kernel_launch(void* const* d_in, const int* in_sizes, int n_in,
                              void* d_out, int out_size)
{
    (void)in_sizes; (void)n_in;
    const float* x   = (const float*)d_in[0];
    const float* Wg  = (const float*)d_in[1];
    const float* bg  = (const float*)d_in[2];
    const float* Wh  = (const float*)d_in[3];
    const float* bh  = (const float*)d_in[4];
    const float* Wo1 = (const float*)d_in[5];
    const float* bo1 = (const float*)d_in[6];
    const float* Wo2 = (const float*)d_in[7];
    const float* bo2 = (const float*)d_in[8];
    float* out = (float*)d_out;

    static int smem_set = 0;
    if (!smem_set) {
        cudaFuncSetAttribute(k_persist, cudaFuncAttributeMaxDynamicSharedMemorySize,
                             SMEM_FLOATS * (int)sizeof(float));
        smem_set = 1;
    }

    k_init<<<512, 256>>>();
    k_pre<<<2048 * 24, 256>>>(x, Wg, bg, Wh, bh);
    k_persist<<<NCTA, 256, SMEM_FLOATS * sizeof(float)>>>(Wg, Wh);
    k_y<<<(BB * TT) / 32, 256>>>(Wo1, bo1, Wo2, bo2, out);

    if (out_size >= BB * TT + BB * HH)
        k_hfinal<<<(BB * HH) / 256, 256>>>(out);
}

// round 8
// speedup vs baseline: 1.1766x; 1.0157x over previous
#include <cuda_runtime.h>
#include <math.h>

#define BB 256
#define TT 512
#define II 512
#define HH 512

typedef unsigned long long u64;

// ---------------- persistent __device__ scratch (no runtime allocation) ----
__device__ float g_h[BB * HH];                    // hidden state
__device__ float g_u[BB * HH];                    // update gate
__device__ float g_rh[BB * HH];                   // reset * h
__device__ unsigned g_bar[2 * TT];                // grid-barrier counters
__device__ float g_sink;                          // prefetch DCE sink
__device__ float g_gx[(size_t)TT * BB * 1024];    // x@Wg_x + bg   [t][b][1024]
__device__ float g_cx[(size_t)TT * BB * HH];      // x@Wh_x + bh   [t][b][512]
__device__ float g_hist[(size_t)TT * BB * HH];    // h history     [t][b][512]

// ---- packed f32x2 helpers ----
__device__ __forceinline__ u64 dup2(float v) {
    u64 r; asm("mov.b64 %0,{%1,%1};" : "=l"(r) : "f"(v)); return r;
}
__device__ __forceinline__ void fma2(u64& d, u64 a, u64 b) {
    asm("fma.rn.f32x2 %0,%1,%2,%0;" : "+l"(d) : "l"(a), "l"(b));
}
__device__ __forceinline__ float2 upk(u64 v) {
    float2 r; asm("mov.b64 {%0,%1},%2;" : "=f"(r.x), "=f"(r.y) : "l"(v)); return r;
}
__device__ __forceinline__ float sigm(float v) { return 1.0f / (1.0f + expf(-v)); }

__device__ __forceinline__ void gridbar(int idx, int nCTA) {
    __syncthreads();
    if (threadIdx.x == 0) {
        __threadfence();
        atomicAdd(&g_bar[idx], 1u);
        while (*(volatile unsigned*)&g_bar[idx] < (unsigned)nCTA) { __nanosleep(32); }
        __threadfence();
    }
    __syncthreads();
}

// ============================================================================
// k_pre: bulk x-projection (off the critical path).
//   C[131072,1536] = x[131072,512] @ [Wg_x | Wh_x] (+bias) -> gx / cx.
// ============================================================================
__global__ __launch_bounds__(256) void k_pre(
    const float* __restrict__ x,
    const float* __restrict__ Wg, const float* __restrict__ bg,
    const float* __restrict__ Wh, const float* __restrict__ bh)
{
    __shared__ __align__(16) float Asd[32][132];
    __shared__ __align__(16) float Bs[32][64];

    const int tid = threadIdx.x;
    const int bid = blockIdx.x;
    const int nt = bid % 24;
    const long m0 = (long)(bid / 24) * 64;

    const float* Bp; long ldb; int gcol0;
    if (nt < 16) { Bp = Wg + nt * 64;        ldb = 1024; gcol0 = nt * 64; }
    else         { Bp = Wh + (nt - 16) * 64; ldb = 512;  gcol0 = 1024 + (nt - 16) * 64; }

    const int arow = tid >> 2, acg = (tid & 3) * 8;
    const int bkr = tid >> 3, bcg = (tid & 7) * 8;
    const int rr = tid >> 4, cc = tid & 15;

    u64 acc[4][2];
#pragma unroll
    for (int r = 0; r < 4; r++) { acc[r][0] = 0ull; acc[r][1] = 0ull; }

    const float* Ab = x + (m0 + arow) * II + acg;
    float4 ra0 = __ldg((const float4*)Ab), ra1 = __ldg((const float4*)(Ab + 4));
    const float* Bb = Bp + (long)bkr * ldb + bcg;
    float4 rb0 = __ldg((const float4*)Bb), rb1 = __ldg((const float4*)(Bb + 4));

    for (int kb = 0; kb < 16; kb++) {
        {
            const float af[8] = {ra0.x, ra0.y, ra0.z, ra0.w, ra1.x, ra1.y, ra1.z, ra1.w};
#pragma unroll
            for (int i = 0; i < 8; i++) *(u64*)&Asd[acg + i][2 * arow] = dup2(af[i]);
        }
        *(float4*)&Bs[bkr][bcg] = rb0;
        *(float4*)&Bs[bkr][bcg + 4] = rb1;
        __syncthreads();

        if (kb < 15) {
            const float* An = Ab + (kb + 1) * 32;
            ra0 = __ldg((const float4*)An); ra1 = __ldg((const float4*)(An + 4));
            const float* Bn = Bb + (long)(kb + 1) * 32 * ldb;
            rb0 = __ldg((const float4*)Bn); rb1 = __ldg((const float4*)(Bn + 4));
        }

#pragma unroll
        for (int k = 0; k < 32; k++) {
            ulonglong2 a01 = *(const ulonglong2*)&Asd[k][8 * rr];
            ulonglong2 a23 = *(const ulonglong2*)&Asd[k][8 * rr + 4];
            ulonglong2 bv  = *(const ulonglong2*)&Bs[k][4 * cc];
            fma2(acc[0][0], a01.x, bv.x); fma2(acc[0][1], a01.x, bv.y);
            fma2(acc[1][0], a01.y, bv.x); fma2(acc[1][1], a01.y, bv.y);
            fma2(acc[2][0], a23.x, bv.x); fma2(acc[2][1], a23.x, bv.y);
            fma2(acc[3][0], a23.y, bv.x); fma2(acc[3][1], a23.y, bv.y);
        }
        __syncthreads();
    }

    const int gcol = gcol0 + 4 * cc;
    float4 bias;
    if (gcol0 < 1024) bias = *(const float4*)&bg[gcol];
    else              bias = *(const float4*)&bh[gcol - 1024];

#pragma unroll
    for (int r = 0; r < 4; r++) {
        const long row = m0 + 4 * rr + r;          // row = b*512 + t
        const long b = row >> 9, t = row & 511;
        float2 c0 = upk(acc[r][0]), c1 = upk(acc[r][1]);
        float4 v = make_float4(c0.x + bias.x, c0.y + bias.y, c1.x + bias.z, c1.y + bias.w);
        if (gcol0 < 1024) *(float4*)&g_gx[(t * BB + b) * 1024 + gcol] = v;
        else              *(float4*)&g_cx[(t * BB + b) * 512 + (gcol - 1024)] = v;
    }
}

// ============================================================================
// k_persist: 512 steps, grid = nsm (>=148 avoids the low-grid issue throttle).
// CTAs 0..127 compute; the rest prefetch next step's gx/cx into L2.
// Double-buffered A staging: ONE __syncthreads per k-block, 2-deep LDG
// pipeline. AS_LD=132 (multiple of 4 -> 16B LDS alignment is legal).
// Dynamic smem: B1[512][32] | B2[512][32] | Asd[2][32][132]  (~161 KB)
// ============================================================================
#define AS_LD 132
#define ABUF  (32 * AS_LD)
#define SM_B1 0
#define SM_B2 16384
#define SM_AS 32768
#define SMEM_FLOATS (32768 + 2 * ABUF)

__global__ __launch_bounds__(256, 1) void k_persist(
    const float* __restrict__ Wg, const float* __restrict__ Wh, int nCTA)
{
    extern __shared__ __align__(16) float sm[];
    float* B1s = sm + SM_B1;
    float* B2s = sm + SM_B2;
    float* Asd = sm + SM_AS;

    const int tid = threadIdx.x;
    const int c = blockIdx.x;
    const bool cw = (c < 128);
    const int nHelp = nCTA - 128;

    // phase-1 tile (64 x 32 of [256 x 1024]); phase-2 tile (32 x 32 of [256 x 512])
    const int m0 = (c >> 5) * 64;
    const int n0 = (c & 31) * 32;
    const int m0b = (c >> 4) * 32;
    const int n0b = (c & 15) * 32;

    if (cw) {   // resident weight slices, loaded once
        const int r0 = tid >> 3, c4 = (tid & 7) * 4;
        for (int rep = 0; rep < 16; rep++) {
            const int krow = rep * 32 + r0;
            *(float4*)&B1s[krow * 32 + c4] = __ldg((const float4*)&Wg[(size_t)(512 + krow) * 1024 + n0 + c4]);
            *(float4*)&B2s[krow * 32 + c4] = __ldg((const float4*)&Wh[(size_t)(512 + krow) * 512 + n0b + c4]);
        }
    }
    __syncthreads();

    const int arow = tid >> 2, acg = (tid & 3) * 8;    // phase1 A: 64 rows x 32 k
    const int rr1 = tid >> 3, cc1 = tid & 7;           // phase1: 2 rows x 4 cols
    const int arow2 = tid >> 3, acg2 = (tid & 7) * 4;  // phase2 A: 32 rows x 32 k
    const int rr2 = tid >> 4, cc2 = tid & 15;          // phase2: 2 rows x 2 cols

    for (int t = 0; t < TT; t++) {
        // =================== Phase 1: h @ Wg_h ===================
        if (cw) {
            const int b0 = m0 + 2 * rr1, nn = n0 + 4 * cc1;
            const size_t gxo = ((size_t)t * BB + b0) * 1024 + nn;
            float4 gx0 = __ldg((const float4*)&g_gx[gxo]);
            float4 gx1 = __ldg((const float4*)&g_gx[gxo + 1024]);
            float4 h0, h1;
            if (n0 >= 512) {
                h0 = __ldcg((const float4*)&g_h[(size_t)b0 * 512 + (nn - 512)]);
                h1 = __ldcg((const float4*)&g_h[(size_t)(b0 + 1) * 512 + (nn - 512)]);
            }

            const float* Ab = g_h + (size_t)(m0 + arow) * 512 + acg;
            float4 ca0 = __ldcg((const float4*)Ab), ca1 = __ldcg((const float4*)(Ab + 4));
            {   // stage kb=0 into buf0 (gridbar/weight-sync precedes -> safe)
                const float af[8] = {ca0.x, ca0.y, ca0.z, ca0.w, ca1.x, ca1.y, ca1.z, ca1.w};
#pragma unroll
                for (int i = 0; i < 8; i++) *(u64*)&Asd[(acg + i) * AS_LD + 2 * arow] = dup2(af[i]);
            }
            float4 na0 = __ldcg((const float4*)(Ab + 32)), na1 = __ldcg((const float4*)(Ab + 36));

            u64 a00 = 0, a01v = 0, a10 = 0, a11 = 0;
            for (int kb = 0; kb < 16; kb++) {
                __syncthreads();
                if (kb < 15) {
                    float* dst = Asd + ((kb + 1) & 1) * ABUF;
                    const float af[8] = {na0.x, na0.y, na0.z, na0.w, na1.x, na1.y, na1.z, na1.w};
#pragma unroll
                    for (int i = 0; i < 8; i++) *(u64*)&dst[(acg + i) * AS_LD + 2 * arow] = dup2(af[i]);
                    if (kb < 14) {
                        const float* An = Ab + (kb + 2) * 32;
                        na0 = __ldcg((const float4*)An); na1 = __ldcg((const float4*)(An + 4));
                    }
                }
                const float* Ak = Asd + (kb & 1) * ABUF;
                const float* Bk = B1s + kb * 1024;
#pragma unroll
                for (int k = 0; k < 32; k++) {
                    ulonglong2 a = *(const ulonglong2*)&Ak[k * AS_LD + 4 * rr1];
                    ulonglong2 b = *(const ulonglong2*)&Bk[k * 32 + 4 * cc1];
                    fma2(a00, a.x, b.x); fma2(a01v, a.x, b.y);
                    fma2(a10, a.y, b.x); fma2(a11, a.y, b.y);
                }
            }

            float2 p00 = upk(a00), p01 = upk(a01v), p10 = upk(a10), p11 = upk(a11);
            float4 v0 = make_float4(sigm(p00.x + gx0.x), sigm(p00.y + gx0.y),
                                    sigm(p01.x + gx0.z), sigm(p01.y + gx0.w));
            float4 v1 = make_float4(sigm(p10.x + gx1.x), sigm(p10.y + gx1.y),
                                    sigm(p11.x + gx1.z), sigm(p11.y + gx1.w));
            if (n0 < 512) {
                __stcg((float4*)&g_u[(size_t)b0 * 512 + nn], v0);
                __stcg((float4*)&g_u[(size_t)(b0 + 1) * 512 + nn], v1);
            } else {
                float4 r0 = make_float4(v0.x * h0.x, v0.y * h0.y, v0.z * h0.z, v0.w * h0.w);
                float4 r1 = make_float4(v1.x * h1.x, v1.y * h1.y, v1.z * h1.z, v1.w * h1.w);
                __stcg((float4*)&g_rh[(size_t)b0 * 512 + (nn - 512)], r0);
                __stcg((float4*)&g_rh[(size_t)(b0 + 1) * 512 + (nn - 512)], r1);
            }
        } else if (t + 1 < TT && nHelp > 0) {
            // helper: warm next step's gx into L2
            float s = 0.f;
            const float4* pg = (const float4*)(g_gx + (size_t)(t + 1) * BB * 1024);
            for (int i = (c - 128) * 256 + tid; i < BB * 1024 / 4; i += nHelp * 256) {
                float4 v = __ldcg(pg + i); s += v.x + v.y + v.z + v.w;
            }
            if (s == 1.2345e30f) g_sink = s;
        }
        gridbar(2 * t + 0, nCTA);

        // =================== Phase 2: rh @ Wh_h ===================
        if (cw) {
            const int b0 = m0b + 2 * rr2, nn = n0b + 2 * cc2;
            const size_t cxo = ((size_t)t * BB + b0) * 512 + nn;
            float2 cx0 = __ldg((const float2*)&g_cx[cxo]);
            float2 cx1 = __ldg((const float2*)&g_cx[cxo + 512]);
            float2 u0 = __ldcg((const float2*)&g_u[(size_t)b0 * 512 + nn]);
            float2 u1 = __ldcg((const float2*)&g_u[(size_t)(b0 + 1) * 512 + nn]);
            float2 h0 = __ldcg((const float2*)&g_h[(size_t)b0 * 512 + nn]);
            float2 h1 = __ldcg((const float2*)&g_h[(size_t)(b0 + 1) * 512 + nn]);

            const float* Ab = g_rh + (size_t)(m0b + arow2) * 512 + acg2;
            float4 ca = __ldcg((const float4*)Ab);
            {
                const float af[4] = {ca.x, ca.y, ca.z, ca.w};
#pragma unroll
                for (int i = 0; i < 4; i++) *(u64*)&Asd[(acg2 + i) * AS_LD + 2 * arow2] = dup2(af[i]);
            }
            float4 na = __ldcg((const float4*)(Ab + 32));

            u64 a0 = 0, a1 = 0;
            for (int kb = 0; kb < 16; kb++) {
                __syncthreads();
                if (kb < 15) {
                    float* dst = Asd + ((kb + 1) & 1) * ABUF;
                    const float af[4] = {na.x, na.y, na.z, na.w};
#pragma unroll
                    for (int i = 0; i < 4; i++) *(u64*)&dst[(acg2 + i) * AS_LD + 2 * arow2] = dup2(af[i]);
                    if (kb < 14) na = __ldcg((const float4*)(Ab + (kb + 2) * 32));
                }
                const float* Ak = Asd + (kb & 1) * ABUF;
                const float* Bk = B2s + kb * 1024;
#pragma unroll
                for (int k = 0; k < 32; k++) {
                    ulonglong2 a = *(const ulonglong2*)&Ak[k * AS_LD + 4 * rr2];
                    u64 b = *(const u64*)&Bk[k * 32 + 2 * cc2];
                    fma2(a0, a.x, b); fma2(a1, a.y, b);
                }
            }

            float2 p0 = upk(a0), p1 = upk(a1);
            float c00 = tanhf(p0.x + cx0.x), c01 = tanhf(p0.y + cx0.y);
            float c10 = tanhf(p1.x + cx1.x), c11 = tanhf(p1.y + cx1.y);
            float2 hn0 = make_float2(fmaf(u0.x, c00 - h0.x, h0.x), fmaf(u0.y, c01 - h0.y, h0.y));
            float2 hn1 = make_float2(fmaf(u1.x, c10 - h1.x, h1.x), fmaf(u1.y, c11 - h1.y, h1.y));
            __stcg((float2*)&g_h[(size_t)b0 * 512 + nn], hn0);
            __stcg((float2*)&g_h[(size_t)(b0 + 1) * 512 + nn], hn1);
            const size_t ho = ((size_t)t * BB + b0) * 512 + nn;
            *(float2*)&g_hist[ho] = hn0;
            *(float2*)&g_hist[ho + 512] = hn1;
        } else if (t + 1 < TT && nHelp > 0) {
            // helper: warm next step's cx into L2
            float s = 0.f;
            const float4* pc = (const float4*)(g_cx + (size_t)(t + 1) * BB * 512);
            for (int i = (c - 128) * 256 + tid; i < BB * 512 / 4; i += nHelp * 256) {
                float4 v = __ldcg(pc + i); s += v.x + v.y + v.z + v.w;
            }
            if (s == 1.2345e30f) g_sink = s;
        }
        gridbar(2 * t + 1, nCTA);
    }
}

// ============================================================================
// k_y: output head off the critical path.
// ============================================================================
__global__ __launch_bounds__(256) void k_y(
    const float* __restrict__ Wo1, const float* __restrict__ bo1,
    const float* __restrict__ Wo2, const float* __restrict__ bo2,
    float* __restrict__ out)
{
    __shared__ __align__(16) float Asd[32][68];
    __shared__ __align__(16) float Bs[32][256];

    const int tid = threadIdx.x;
    const long m0 = (long)blockIdx.x * 32;
    const int lk = tid & 31, lm = tid >> 5;
    const int rg = tid >> 5, cg = tid & 31;

    u64 acc[4][4];
#pragma unroll
    for (int r = 0; r < 4; r++)
#pragma unroll
        for (int p = 0; p < 4; p++) acc[r][p] = 0ull;

    for (int k0 = 0; k0 < HH; k0 += 32) {
        const float* ap = g_hist + m0 * HH + k0 + lk;
#pragma unroll
        for (int i = 0; i < 4; i++) {
            float v = ap[(long)(lm + 8 * i) * HH];
            *(u64*)&Asd[lk][2 * (lm + 8 * i)] = dup2(v);
        }
        const int bn = (tid & 63) * 4;
        const int bkk = tid >> 6;
#pragma unroll
        for (int j = 0; j < 8; j++) {
            float4 v = *(const float4*)&Wo1[(long)(k0 + bkk + 4 * j) * 256 + bn];
            *(float4*)&Bs[bkk + 4 * j][bn] = v;
        }
        __syncthreads();

#pragma unroll
        for (int k = 0; k < 32; k++) {
            ulonglong2 a01 = *(const ulonglong2*)&Asd[k][8 * rg];
            ulonglong2 a23 = *(const ulonglong2*)&Asd[k][8 * rg + 4];
            ulonglong2 b01 = *(const ulonglong2*)&Bs[k][8 * cg];
            ulonglong2 b23 = *(const ulonglong2*)&Bs[k][8 * cg + 4];
            fma2(acc[0][0], a01.x, b01.x); fma2(acc[0][1], a01.x, b01.y);
            fma2(acc[0][2], a01.x, b23.x); fma2(acc[0][3], a01.x, b23.y);
            fma2(acc[1][0], a01.y, b01.x); fma2(acc[1][1], a01.y, b01.y);
            fma2(acc[1][2], a01.y, b23.x); fma2(acc[1][3], a01.y, b23.y);
            fma2(acc[2][0], a23.x, b01.x); fma2(acc[2][1], a23.x, b01.y);
            fma2(acc[2][2], a23.x, b23.x); fma2(acc[2][3], a23.x, b23.y);
            fma2(acc[3][0], a23.y, b01.x); fma2(acc[3][1], a23.y, b01.y);
            fma2(acc[3][2], a23.y, b23.x); fma2(acc[3][3], a23.y, b23.y);
        }
        __syncthreads();
    }

    float b1[8], w2[8];
#pragma unroll
    for (int q = 0; q < 8; q++) { const int n = 8 * cg + q; b1[q] = bo1[n]; w2[q] = Wo2[n]; }
    const float bo2v = bo2[0];

#pragma unroll
    for (int r = 0; r < 4; r++) {
        float part = 0.f;
#pragma unroll
        for (int p = 0; p < 4; p++) {
            float2 z = upk(acc[r][p]);
            float z0 = fmaxf(z.x + b1[2 * p], 0.f);
            float z1 = fmaxf(z.y + b1[2 * p + 1], 0.f);
            part = fmaf(z0, w2[2 * p], part);
            part = fmaf(z1, w2[2 * p + 1], part);
        }
#pragma unroll
        for (int o = 16; o > 0; o >>= 1) part += __shfl_xor_sync(0xffffffffu, part, o);
        if (cg == 0) {
            const long m = m0 + 4 * rg + r;       // m = t*256 + b
            const int b = (int)(m & 255);
            const int tt = (int)(m >> 8);
            out[(long)b * TT + tt] = part + bo2v; // ys[b][t][0]
        }
    }
}

__global__ void k_init() {
    const int i = blockIdx.x * 256 + threadIdx.x;
    if (i < BB * HH) g_h[i] = 0.f;
    if (i < 2 * TT) g_bar[i] = 0u;
}

__global__ void k_hfinal(float* __restrict__ out) {
    const int i = blockIdx.x * 256 + threadIdx.x;
    out[(long)BB * TT + i] = g_h[i];
}

// ============================================================================
extern "C" void kernel_launch(void* const* d_in, const int* in_sizes, int n_in,
                              void* d_out, int out_size)
{
    (void)in_sizes; (void)n_in;
    const float* x   = (const float*)d_in[0];
    const float* Wg  = (const float*)d_in[1];
    const float* bg  = (const float*)d_in[2];
    const float* Wh  = (const float*)d_in[3];
    const float* bh  = (const float*)d_in[4];
    const float* Wo1 = (const float*)d_in[5];
    const float* bo1 = (const float*)d_in[6];
    const float* Wo2 = (const float*)d_in[7];
    const float* bo2 = (const float*)d_in[8];
    float* out = (float*)d_out;

    int dev = 0, nsm = 0;
    cudaGetDevice(&dev);
    cudaDeviceGetAttribute(&nsm, cudaDevAttrMultiProcessorCount, dev);
    if (nsm <= 0) nsm = 128;
    int nCTA = (nsm >= 128) ? nsm : 128;   // one wave; all CTAs resident

    cudaFuncSetAttribute(k_persist, cudaFuncAttributeMaxDynamicSharedMemorySize,
                         SMEM_FLOATS * (int)sizeof(float));

    k_init<<<512, 256>>>();
    k_pre<<<2048 * 24, 256>>>(x, Wg, bg, Wh, bh);
    k_persist<<<nCTA, 256, SMEM_FLOATS * sizeof(float)>>>(Wg, Wh, nCTA);
    k_y<<<(BB * TT) / 32, 256>>>(Wo1, bo1, Wo2, bo2, out);

    if (out_size >= BB * TT + BB * HH)
        k_hfinal<<<(BB * HH) / 256, 256>>>(out);
}

// round 10
// speedup vs baseline: 1.2279x; 1.0436x over previous
#include <cuda_runtime.h>
#include <math.h>

#define BB 256
#define TT 512
#define II 512
#define HH 512

typedef unsigned long long u64;

// ---------------- persistent __device__ scratch ----------------
__device__ float g_h[BB * HH];                    // hidden state
__device__ float g_u[BB * HH];                    // update gate
__device__ float g_rh[BB * HH];                   // reset * h
__device__ unsigned g_c1[4 * TT];                 // phase1-done counters [t*4+band]
__device__ unsigned g_c2[4 * TT];                 // phase2-done counters
__device__ float g_gx[(size_t)TT * BB * 1024];    // x@Wg_x + bg
__device__ float g_cx[(size_t)TT * BB * HH];      // x@Wh_x + bh
__device__ float g_hist[(size_t)TT * BB * HH];    // h history

// ---- packed f32x2 helpers ----
__device__ __forceinline__ u64 dup2(float v) {
    u64 r; asm("mov.b64 %0,{%1,%1};" : "=l"(r) : "f"(v)); return r;
}
__device__ __forceinline__ void fma2(u64& d, u64 a, u64 b) {
    asm("fma.rn.f32x2 %0,%1,%2,%0;" : "+l"(d) : "l"(a), "l"(b));
}
__device__ __forceinline__ float2 upk(u64 v) {
    float2 r; asm("mov.b64 {%0,%1},%2;" : "=f"(r.x), "=f"(r.y) : "l"(v)); return r;
}
__device__ __forceinline__ float sigm(float v) { return 1.0f / (1.0f + expf(-v)); }

// ---- band-local producer/consumer sync (32 arrivals per counter) ----
__device__ __forceinline__ void band_arrive(unsigned* ctr) {
    __threadfence();          // order this CTA's stores before the count
    __syncthreads();
    if (threadIdx.x == 0) atomicAdd(ctr, 1u);
}
__device__ __forceinline__ void band_wait(unsigned* ctr, unsigned tgt) {
    if (threadIdx.x == 0) {
        while (*(volatile unsigned*)ctr < tgt) { __nanosleep(20); }
        __threadfence();
    }
    __syncthreads();
}

// ============================================================================
// k_pre: bulk x-projection (off the critical path).
// A-staging uses conflict-free k-row mapping: thread (am=tid>>2, g=tid&3)
// stages k in {8j+2g, 8j+2g+1} -> distinct STS banks per 16-lane phase.
// ============================================================================
__global__ __launch_bounds__(256) void k_pre(
    const float* __restrict__ x,
    const float* __restrict__ Wg, const float* __restrict__ bg,
    const float* __restrict__ Wh, const float* __restrict__ bh)
{
    __shared__ __align__(16) float Asd[32][132];
    __shared__ __align__(16) float Bs[32][64];

    const int tid = threadIdx.x;
    const int bid = blockIdx.x;
    const int nt = bid % 24;
    const long m0 = (long)(bid / 24) * 64;

    const float* Bp; long ldb; int gcol0;
    if (nt < 16) { Bp = Wg + nt * 64;        ldb = 1024; gcol0 = nt * 64; }
    else         { Bp = Wh + (nt - 16) * 64; ldb = 512;  gcol0 = 1024 + (nt - 16) * 64; }

    const int g1 = tid & 3, am = tid >> 2;            // A staging map
    const int bkr = tid >> 3, bcg = (tid & 7) * 8;    // B loader
    const int rr = tid >> 4, cc = tid & 15;           // compute

    u64 acc[4][2];
#pragma unroll
    for (int r = 0; r < 4; r++) { acc[r][0] = 0ull; acc[r][1] = 0ull; }

    const float* Ab = x + (m0 + am) * II + 2 * g1;
    float2 pa[4];
#pragma unroll
    for (int j = 0; j < 4; j++) pa[j] = __ldg((const float2*)(Ab + 8 * j));
    const float* Bb = Bp + (long)bkr * ldb + bcg;
    float4 rb0 = __ldg((const float4*)Bb), rb1 = __ldg((const float4*)(Bb + 4));

    for (int kb = 0; kb < 16; kb++) {
#pragma unroll
        for (int j = 0; j < 4; j++) {
            *(u64*)&Asd[8 * j + 2 * g1][2 * am]     = dup2(pa[j].x);
            *(u64*)&Asd[8 * j + 2 * g1 + 1][2 * am] = dup2(pa[j].y);
        }
        *(float4*)&Bs[bkr][bcg] = rb0;
        *(float4*)&Bs[bkr][bcg + 4] = rb1;
        __syncthreads();

        if (kb < 15) {
            const float* An = Ab + (kb + 1) * 32;
#pragma unroll
            for (int j = 0; j < 4; j++) pa[j] = __ldg((const float2*)(An + 8 * j));
            const float* Bn = Bb + (long)(kb + 1) * 32 * ldb;
            rb0 = __ldg((const float4*)Bn); rb1 = __ldg((const float4*)(Bn + 4));
        }

#pragma unroll
        for (int k = 0; k < 32; k++) {
            ulonglong2 a01 = *(const ulonglong2*)&Asd[k][8 * rr];
            ulonglong2 a23 = *(const ulonglong2*)&Asd[k][8 * rr + 4];
            ulonglong2 bv  = *(const ulonglong2*)&Bs[k][4 * cc];
            fma2(acc[0][0], a01.x, bv.x); fma2(acc[0][1], a01.x, bv.y);
            fma2(acc[1][0], a01.y, bv.x); fma2(acc[1][1], a01.y, bv.y);
            fma2(acc[2][0], a23.x, bv.x); fma2(acc[2][1], a23.x, bv.y);
            fma2(acc[3][0], a23.y, bv.x); fma2(acc[3][1], a23.y, bv.y);
        }
        __syncthreads();
    }

    const int gcol = gcol0 + 4 * cc;
    float4 bias;
    if (gcol0 < 1024) bias = *(const float4*)&bg[gcol];
    else              bias = *(const float4*)&bh[gcol - 1024];

#pragma unroll
    for (int r = 0; r < 4; r++) {
        const long row = m0 + 4 * rr + r;          // row = b*512 + t
        const long b = row >> 9, t = row & 511;
        float2 c0 = upk(acc[r][0]), c1 = upk(acc[r][1]);
        float4 v = make_float4(c0.x + bias.x, c0.y + bias.y, c1.x + bias.z, c1.y + bias.w);
        if (gcol0 < 1024) *(float4*)&g_gx[(t * BB + b) * 1024 + gcol] = v;
        else              *(float4*)&g_cx[(t * BB + b) * 512 + (gcol - 1024)] = v;
    }
}

// ============================================================================
// k_persist: 512 steps; the 4 row-bands (64 rows each) are fully independent
// chains synced by band-local 32-arrival counters (no global barrier).
// Conflict-free A staging; double-buffered; one __syncthreads per k-block.
// ============================================================================
#define AS_LD 132
#define ABUF  (32 * AS_LD)
#define SMEM_FLOATS (32768 + 2 * ABUF)

__global__ __launch_bounds__(256, 1) void k_persist(
    const float* __restrict__ Wg, const float* __restrict__ Wh)
{
    extern __shared__ __align__(16) float sm[];
    float* B1s = sm;
    float* B2s = sm + 16384;
    float* Asd = sm + 32768;

    const int tid = threadIdx.x;
    const int c = blockIdx.x;
    if (c >= 128) return;
    const int band = c >> 5;

    const int m0 = band * 64;                 // phase1 rows
    const int n0 = (c & 31) * 32;             // phase1 cols (of 1024)
    const int m0b = (c >> 4) * 32;            // phase2 rows (same band)
    const int n0b = (c & 15) * 32;            // phase2 cols (of 512)

    {   // resident weight slices, loaded once
        const int r0 = tid >> 3, c4 = (tid & 7) * 4;
        for (int rep = 0; rep < 16; rep++) {
            const int krow = rep * 32 + r0;
            *(float4*)&B1s[krow * 32 + c4] = __ldg((const float4*)&Wg[(size_t)(512 + krow) * 1024 + n0 + c4]);
            *(float4*)&B2s[krow * 32 + c4] = __ldg((const float4*)&Wh[(size_t)(512 + krow) * 512 + n0b + c4]);
        }
    }
    __syncthreads();

    // staging maps (conflict-free STS)
    const int g1 = tid & 3, am = tid >> 2;              // phase1: row am, k=8j+2g1+e
    const int m2 = tid >> 3;                            // phase2: row m2
    const int g2e = 2 * (tid & 3) + ((tid >> 2) & 1);   // phase2: k=8j+g2e
    // compute maps
    const int rr1 = tid >> 3, cc1 = tid & 7;
    const int rr2 = tid >> 4, cc2 = tid & 15;

    for (int t = 0; t < TT; t++) {
        if (t > 0) band_wait(&g_c2[(t - 1) * 4 + band], 32);

        // =================== Phase 1: h @ Wg_h ===================
        {
            const int b0 = m0 + 2 * rr1, nn = n0 + 4 * cc1;
            const size_t gxo = ((size_t)t * BB + b0) * 1024 + nn;
            float4 gx0 = __ldg((const float4*)&g_gx[gxo]);
            float4 gx1 = __ldg((const float4*)&g_gx[gxo + 1024]);
            float4 h0, h1;
            if (n0 >= 512) {
                h0 = __ldcg((const float4*)&g_h[(size_t)b0 * 512 + (nn - 512)]);
                h1 = __ldcg((const float4*)&g_h[(size_t)(b0 + 1) * 512 + (nn - 512)]);
            }

            const float* Ab = g_h + (size_t)(m0 + am) * 512 + 2 * g1;
            float2 pa[4], na[4];
#pragma unroll
            for (int j = 0; j < 4; j++) pa[j] = __ldcg((const float2*)(Ab + 8 * j));
#pragma unroll
            for (int j = 0; j < 4; j++) {   // stage kb0 -> buf0
                *(u64*)&Asd[(8 * j + 2 * g1) * AS_LD + 2 * am]     = dup2(pa[j].x);
                *(u64*)&Asd[(8 * j + 2 * g1 + 1) * AS_LD + 2 * am] = dup2(pa[j].y);
            }
#pragma unroll
            for (int j = 0; j < 4; j++) na[j] = __ldcg((const float2*)(Ab + 32 + 8 * j));

            u64 a00 = 0, a01v = 0, a10 = 0, a11 = 0;
            for (int kb = 0; kb < 16; kb++) {
                __syncthreads();
                if (kb < 15) {
                    float* dst = Asd + ((kb + 1) & 1) * ABUF;
#pragma unroll
                    for (int j = 0; j < 4; j++) {
                        *(u64*)&dst[(8 * j + 2 * g1) * AS_LD + 2 * am]     = dup2(na[j].x);
                        *(u64*)&dst[(8 * j + 2 * g1 + 1) * AS_LD + 2 * am] = dup2(na[j].y);
                    }
                    if (kb < 14) {
                        const float* An = Ab + (kb + 2) * 32;
#pragma unroll
                        for (int j = 0; j < 4; j++) na[j] = __ldcg((const float2*)(An + 8 * j));
                    }
                }
                const float* Ak = Asd + (kb & 1) * ABUF;
                const float* Bk = B1s + kb * 1024;
#pragma unroll
                for (int k = 0; k < 32; k++) {
                    ulonglong2 a = *(const ulonglong2*)&Ak[k * AS_LD + 4 * rr1];
                    ulonglong2 b = *(const ulonglong2*)&Bk[k * 32 + 4 * cc1];
                    fma2(a00, a.x, b.x); fma2(a01v, a.x, b.y);
                    fma2(a10, a.y, b.x); fma2(a11, a.y, b.y);
                }
            }

            float2 p00 = upk(a00), p01 = upk(a01v), p10 = upk(a10), p11 = upk(a11);
            float4 v0 = make_float4(sigm(p00.x + gx0.x), sigm(p00.y + gx0.y),
                                    sigm(p01.x + gx0.z), sigm(p01.y + gx0.w));
            float4 v1 = make_float4(sigm(p10.x + gx1.x), sigm(p10.y + gx1.y),
                                    sigm(p11.x + gx1.z), sigm(p11.y + gx1.w));
            if (n0 < 512) {
                __stcg((float4*)&g_u[(size_t)b0 * 512 + nn], v0);
                __stcg((float4*)&g_u[(size_t)(b0 + 1) * 512 + nn], v1);
            } else {
                float4 r0 = make_float4(v0.x * h0.x, v0.y * h0.y, v0.z * h0.z, v0.w * h0.w);
                float4 r1 = make_float4(v1.x * h1.x, v1.y * h1.y, v1.z * h1.z, v1.w * h1.w);
                __stcg((float4*)&g_rh[(size_t)b0 * 512 + (nn - 512)], r0);
                __stcg((float4*)&g_rh[(size_t)(b0 + 1) * 512 + (nn - 512)], r1);
            }
        }
        band_arrive(&g_c1[t * 4 + band]);
        band_wait(&g_c1[t * 4 + band], 32);

        // =================== Phase 2: rh @ Wh_h ===================
        {
            const int b0 = m0b + 2 * rr2, nn = n0b + 2 * cc2;
            const size_t cxo = ((size_t)t * BB + b0) * 512 + nn;
            float2 cx0 = __ldg((const float2*)&g_cx[cxo]);
            float2 cx1 = __ldg((const float2*)&g_cx[cxo + 512]);
            float2 u0 = __ldcg((const float2*)&g_u[(size_t)b0 * 512 + nn]);
            float2 u1 = __ldcg((const float2*)&g_u[(size_t)(b0 + 1) * 512 + nn]);
            float2 h0 = __ldcg((const float2*)&g_h[(size_t)b0 * 512 + nn]);
            float2 h1 = __ldcg((const float2*)&g_h[(size_t)(b0 + 1) * 512 + nn]);

            const float* Ab2 = g_rh + (size_t)(m0b + m2) * 512 + g2e;
            float ra[4], nb[4];
#pragma unroll
            for (int j = 0; j < 4; j++) ra[j] = __ldcg(Ab2 + 8 * j);
#pragma unroll
            for (int j = 0; j < 4; j++)   // stage kb0 -> buf0
                *(u64*)&Asd[(8 * j + g2e) * AS_LD + 2 * m2] = dup2(ra[j]);
#pragma unroll
            for (int j = 0; j < 4; j++) nb[j] = __ldcg(Ab2 + 32 + 8 * j);

            u64 a0 = 0, a1 = 0;
            for (int kb = 0; kb < 16; kb++) {
                __syncthreads();
                if (kb < 15) {
                    float* dst = Asd + ((kb + 1) & 1) * ABUF;
#pragma unroll
                    for (int j = 0; j < 4; j++)
                        *(u64*)&dst[(8 * j + g2e) * AS_LD + 2 * m2] = dup2(nb[j]);
                    if (kb < 14) {
#pragma unroll
                        for (int j = 0; j < 4; j++) nb[j] = __ldcg(Ab2 + (kb + 2) * 32 + 8 * j);
                    }
                }
                const float* Ak = Asd + (kb & 1) * ABUF;
                const float* Bk = B2s + kb * 1024;
#pragma unroll
                for (int k = 0; k < 32; k++) {
                    ulonglong2 a = *(const ulonglong2*)&Ak[k * AS_LD + 4 * rr2];
                    u64 b = *(const u64*)&Bk[k * 32 + 2 * cc2];
                    fma2(a0, a.x, b); fma2(a1, a.y, b);
                }
            }

            float2 p0 = upk(a0), p1 = upk(a1);
            float c00 = tanhf(p0.x + cx0.x), c01 = tanhf(p0.y + cx0.y);
            float c10 = tanhf(p1.x + cx1.x), c11 = tanhf(p1.y + cx1.y);
            float2 hn0 = make_float2(fmaf(u0.x, c00 - h0.x, h0.x), fmaf(u0.y, c01 - h0.y, h0.y));
            float2 hn1 = make_float2(fmaf(u1.x, c10 - h1.x, h1.x), fmaf(u1.y, c11 - h1.y, h1.y));
            __stcg((float2*)&g_h[(size_t)b0 * 512 + nn], hn0);
            __stcg((float2*)&g_h[(size_t)(b0 + 1) * 512 + nn], hn1);
            const size_t ho = ((size_t)t * BB + b0) * 512 + nn;
            *(float2*)&g_hist[ho] = hn0;
            *(float2*)&g_hist[ho + 512] = hn1;
        }
        band_arrive(&g_c2[t * 4 + band]);
    }
}

// ============================================================================
// k_y: output head off the critical path (unchanged).
// ============================================================================
__global__ __launch_bounds__(256) void k_y(
    const float* __restrict__ Wo1, const float* __restrict__ bo1,
    const float* __restrict__ Wo2, const float* __restrict__ bo2,
    float* __restrict__ out)
{
    __shared__ __align__(16) float Asd[32][68];
    __shared__ __align__(16) float Bs[32][256];

    const int tid = threadIdx.x;
    const long m0 = (long)blockIdx.x * 32;
    const int lk = tid & 31, lm = tid >> 5;
    const int rg = tid >> 5, cg = tid & 31;

    u64 acc[4][4];
#pragma unroll
    for (int r = 0; r < 4; r++)
#pragma unroll
        for (int p = 0; p < 4; p++) acc[r][p] = 0ull;

    for (int k0 = 0; k0 < HH; k0 += 32) {
        const float* ap = g_hist + m0 * HH + k0 + lk;
#pragma unroll
        for (int i = 0; i < 4; i++) {
            float v = ap[(long)(lm + 8 * i) * HH];
            *(u64*)&Asd[lk][2 * (lm + 8 * i)] = dup2(v);
        }
        const int bn = (tid & 63) * 4;
        const int bkk = tid >> 6;
#pragma unroll
        for (int j = 0; j < 8; j++) {
            float4 v = *(const float4*)&Wo1[(long)(k0 + bkk + 4 * j) * 256 + bn];
            *(float4*)&Bs[bkk + 4 * j][bn] = v;
        }
        __syncthreads();

#pragma unroll
        for (int k = 0; k < 32; k++) {
            ulonglong2 a01 = *(const ulonglong2*)&Asd[k][8 * rg];
            ulonglong2 a23 = *(const ulonglong2*)&Asd[k][8 * rg + 4];
            ulonglong2 b01 = *(const ulonglong2*)&Bs[k][8 * cg];
            ulonglong2 b23 = *(const ulonglong2*)&Bs[k][8 * cg + 4];
            fma2(acc[0][0], a01.x, b01.x); fma2(acc[0][1], a01.x, b01.y);
            fma2(acc[0][2], a01.x, b23.x); fma2(acc[0][3], a01.x, b23.y);
            fma2(acc[1][0], a01.y, b01.x); fma2(acc[1][1], a01.y, b01.y);
            fma2(acc[1][2], a01.y, b23.x); fma2(acc[1][3], a01.y, b23.y);
            fma2(acc[2][0], a23.x, b01.x); fma2(acc[2][1], a23.x, b01.y);
            fma2(acc[2][2], a23.x, b23.x); fma2(acc[2][3], a23.x, b23.y);
            fma2(acc[3][0], a23.y, b01.x); fma2(acc[3][1], a23.y, b01.y);
            fma2(acc[3][2], a23.y, b23.x); fma2(acc[3][3], a23.y, b23.y);
        }
        __syncthreads();
    }

    float b1[8], w2[8];
#pragma unroll
    for (int q = 0; q < 8; q++) { const int n = 8 * cg + q; b1[q] = bo1[n]; w2[q] = Wo2[n]; }
    const float bo2v = bo2[0];

#pragma unroll
    for (int r = 0; r < 4; r++) {
        float part = 0.f;
#pragma unroll
        for (int p = 0; p < 4; p++) {
            float2 z = upk(acc[r][p]);
            float z0 = fmaxf(z.x + b1[2 * p], 0.f);
            float z1 = fmaxf(z.y + b1[2 * p + 1], 0.f);
            part = fmaf(z0, w2[2 * p], part);
            part = fmaf(z1, w2[2 * p + 1], part);
        }
#pragma unroll
        for (int o = 16; o > 0; o >>= 1) part += __shfl_xor_sync(0xffffffffu, part, o);
        if (cg == 0) {
            const long m = m0 + 4 * rg + r;       // m = t*256 + b
            const int b = (int)(m & 255);
            const int tt = (int)(m >> 8);
            out[(long)b * TT + tt] = part + bo2v; // ys[b][t][0]
        }
    }
}

__global__ void k_init() {
    const int i = blockIdx.x * 256 + threadIdx.x;
    if (i < BB * HH) g_h[i] = 0.f;
    if (i < 4 * TT) { g_c1[i] = 0u; g_c2[i] = 0u; }
}

__global__ void k_hfinal(float* __restrict__ out) {
    const int i = blockIdx.x * 256 + threadIdx.x;
    out[(long)BB * TT + i] = g_h[i];
}

// ============================================================================
extern "C" void kernel_launch(void* const* d_in, const int* in_sizes, int n_in,
                              void* d_out, int out_size)
{
    (void)in_sizes; (void)n_in;
    const float* x   = (const float*)d_in[0];
    const float* Wg  = (const float*)d_in[1];
    const float* bg  = (const float*)d_in[2];
    const float* Wh  = (const float*)d_in[3];
    const float* bh  = (const float*)d_in[4];
    const float* Wo1 = (const float*)d_in[5];
    const float* bo1 = (const float*)d_in[6];
    const float* Wo2 = (const float*)d_in[7];
    const float* bo2 = (const float*)d_in[8];
    float* out = (float*)d_out;

    int dev = 0, nsm = 0;
    cudaGetDevice(&dev);
    cudaDeviceGetAttribute(&nsm, cudaDevAttrMultiProcessorCount, dev);
    int nCTA = (nsm >= 128) ? nsm : 128;   // extras exit immediately

    cudaFuncSetAttribute(k_persist, cudaFuncAttributeMaxDynamicSharedMemorySize,
                         SMEM_FLOATS * (int)sizeof(float));

    k_init<<<512, 256>>>();
    k_pre<<<2048 * 24, 256>>>(x, Wg, bg, Wh, bh);
    k_persist<<<nCTA, 256, SMEM_FLOATS * sizeof(float)>>>(Wg, Wh);
    k_y<<<(BB * TT) / 32, 256>>>(Wo1, bo1, Wo2, bo2, out);

    if (out_size >= BB * TT + BB * HH)
        k_hfinal<<<(BB * HH) / 256, 256>>>(out);
}

// round 11
// speedup vs baseline: 1.3168x; 1.0724x over previous
#include <cuda_runtime.h>
#include <math.h>

#define BB 256
#define TT 512
#define II 512
#define HH 512

typedef unsigned long long u64;

// ---------------- persistent __device__ scratch ----------------
__device__ float g_h[BB * HH];                    // hidden state
__device__ float g_u[BB * HH];                    // update gate
__device__ float g_rh[BB * HH];                   // reset * h
__device__ unsigned g_c1r[4 * TT];                // rh-half phase1 done [t*4+band]
__device__ unsigned g_c1u[4 * TT];                // u-half phase1 done
__device__ unsigned g_c2[4 * TT];                 // phase2 done
__device__ float g_gx[(size_t)TT * BB * 1024];    // x@Wg_x + bg
__device__ float g_cx[(size_t)TT * BB * HH];      // x@Wh_x + bh
__device__ float g_hist[(size_t)TT * BB * HH];    // h history

// ---- packed f32x2 helpers ----
__device__ __forceinline__ u64 dup2(float v) {
    u64 r; asm("mov.b64 %0,{%1,%1};" : "=l"(r) : "f"(v)); return r;
}
__device__ __forceinline__ void fma2(u64& d, u64 a, u64 b) {
    asm("fma.rn.f32x2 %0,%1,%2,%0;" : "+l"(d) : "l"(a), "l"(b));
}
__device__ __forceinline__ float2 upk(u64 v) {
    float2 r; asm("mov.b64 {%0,%1},%2;" : "=f"(r.x), "=f"(r.y) : "l"(v)); return r;
}
__device__ __forceinline__ float sigm(float v) { return 1.0f / (1.0f + expf(-v)); }

// ---- release/acquire counter sync (no 256-thread membar) ----
__device__ __forceinline__ void red_release(unsigned* ctr) {
    asm volatile("red.release.gpu.global.add.u32 [%0],%1;" :: "l"(ctr), "r"(1u) : "memory");
}
__device__ __forceinline__ unsigned ld_acquire(unsigned* ctr) {
    unsigned v;
    asm volatile("ld.acquire.gpu.global.u32 %0,[%1];" : "=r"(v) : "l"(ctr) : "memory");
    return v;
}
__device__ __forceinline__ void band_arrive(unsigned* ctr) {
    __syncthreads();                       // all warps' stores issued
    if (threadIdx.x == 0) red_release(ctr);
}
__device__ __forceinline__ void band_wait(unsigned* ctr, unsigned tgt) {
    if (threadIdx.x == 0) {
        while (ld_acquire(ctr) < tgt) { __nanosleep(20); }
    }
    __syncthreads();
}

// ============================================================================
// k_pre: bulk x-projection (off the critical path) — unchanged.
// ============================================================================
__global__ __launch_bounds__(256) void k_pre(
    const float* __restrict__ x,
    const float* __restrict__ Wg, const float* __restrict__ bg,
    const float* __restrict__ Wh, const float* __restrict__ bh)
{
    __shared__ __align__(16) float Asd[32][132];
    __shared__ __align__(16) float Bs[32][64];

    const int tid = threadIdx.x;
    const int bid = blockIdx.x;
    const int nt = bid % 24;
    const long m0 = (long)(bid / 24) * 64;

    const float* Bp; long ldb; int gcol0;
    if (nt < 16) { Bp = Wg + nt * 64;        ldb = 1024; gcol0 = nt * 64; }
    else         { Bp = Wh + (nt - 16) * 64; ldb = 512;  gcol0 = 1024 + (nt - 16) * 64; }

    const int g1 = tid & 3, am = tid >> 2;
    const int bkr = tid >> 3, bcg = (tid & 7) * 8;
    const int rr = tid >> 4, cc = tid & 15;

    u64 acc[4][2];
#pragma unroll
    for (int r = 0; r < 4; r++) { acc[r][0] = 0ull; acc[r][1] = 0ull; }

    const float* Ab = x + (m0 + am) * II + 2 * g1;
    float2 pa[4];
#pragma unroll
    for (int j = 0; j < 4; j++) pa[j] = __ldg((const float2*)(Ab + 8 * j));
    const float* Bb = Bp + (long)bkr * ldb + bcg;
    float4 rb0 = __ldg((const float4*)Bb), rb1 = __ldg((const float4*)(Bb + 4));

    for (int kb = 0; kb < 16; kb++) {
#pragma unroll
        for (int j = 0; j < 4; j++) {
            *(u64*)&Asd[8 * j + 2 * g1][2 * am]     = dup2(pa[j].x);
            *(u64*)&Asd[8 * j + 2 * g1 + 1][2 * am] = dup2(pa[j].y);
        }
        *(float4*)&Bs[bkr][bcg] = rb0;
        *(float4*)&Bs[bkr][bcg + 4] = rb1;
        __syncthreads();

        if (kb < 15) {
            const float* An = Ab + (kb + 1) * 32;
#pragma unroll
            for (int j = 0; j < 4; j++) pa[j] = __ldg((const float2*)(An + 8 * j));
            const float* Bn = Bb + (long)(kb + 1) * 32 * ldb;
            rb0 = __ldg((const float4*)Bn); rb1 = __ldg((const float4*)(Bn + 4));
        }

#pragma unroll
        for (int k = 0; k < 32; k++) {
            ulonglong2 a01 = *(const ulonglong2*)&Asd[k][8 * rr];
            ulonglong2 a23 = *(const ulonglong2*)&Asd[k][8 * rr + 4];
            ulonglong2 bv  = *(const ulonglong2*)&Bs[k][4 * cc];
            fma2(acc[0][0], a01.x, bv.x); fma2(acc[0][1], a01.x, bv.y);
            fma2(acc[1][0], a01.y, bv.x); fma2(acc[1][1], a01.y, bv.y);
            fma2(acc[2][0], a23.x, bv.x); fma2(acc[2][1], a23.x, bv.y);
            fma2(acc[3][0], a23.y, bv.x); fma2(acc[3][1], a23.y, bv.y);
        }
        __syncthreads();
    }

    const int gcol = gcol0 + 4 * cc;
    float4 bias;
    if (gcol0 < 1024) bias = *(const float4*)&bg[gcol];
    else              bias = *(const float4*)&bh[gcol - 1024];

#pragma unroll
    for (int r = 0; r < 4; r++) {
        const long row = m0 + 4 * rr + r;          // row = b*512 + t
        const long b = row >> 9, t = row & 511;
        float2 c0 = upk(acc[r][0]), c1 = upk(acc[r][1]);
        float4 v = make_float4(c0.x + bias.x, c0.y + bias.y, c1.x + bias.z, c1.y + bias.w);
        if (gcol0 < 1024) *(float4*)&g_gx[(t * BB + b) * 1024 + gcol] = v;
        else              *(float4*)&g_cx[(t * BB + b) * 512 + (gcol - 1024)] = v;
    }
}

// ============================================================================
// k_persist: 512 steps. KEY CHANGE: the A tile is warp-private in both phases
// (warp w computes rows 8w..8w+7 / 4w..4w+3 and stages exactly those rows), so
// GEMM loops run with ZERO __syncthreads — per-warp staging buffers +
// __syncwarp only. Warps drift freely and hide each other's latencies.
// Stride-20 staging rows -> conflict-free STS.64 in both phases.
// smem: B1[512][32] | B2[512][32] | per-warp A staging 8x2x640  (168 KB)
// ============================================================================
#define AS_STRIDE 20
#define AW_BUF    (32 * AS_STRIDE)     // 640 floats per buffer
#define AW_WARP   (2 * AW_BUF)         // double-buffered per warp
#define SMEM_FLOATS (32768 + 8 * AW_WARP)

__global__ __launch_bounds__(256, 1) void k_persist(
    const float* __restrict__ Wg, const float* __restrict__ Wh)
{
    extern __shared__ __align__(16) float sm[];
    float* B1s = sm;
    float* B2s = sm + 16384;
    float* As  = sm + 32768;

    const int tid = threadIdx.x;
    const int c = blockIdx.x;
    if (c >= 128) return;
    const int band = c >> 5;

    const int m0 = band * 64;                 // phase1 rows
    const int n0 = (c & 31) * 32;             // phase1 cols (of 1024)
    const int m0b = (c >> 4) * 32;            // phase2 rows
    const int n0b = (c & 15) * 32;            // phase2 cols (of 512)
    const bool is_rh = (n0 >= 512);

    {   // resident weight slices, loaded once
        const int r0 = tid >> 3, c4 = (tid & 7) * 4;
        for (int rep = 0; rep < 16; rep++) {
            const int krow = rep * 32 + r0;
            *(float4*)&B1s[krow * 32 + c4] = __ldg((const float4*)&Wg[(size_t)(512 + krow) * 1024 + n0 + c4]);
            *(float4*)&B2s[krow * 32 + c4] = __ldg((const float4*)&Wh[(size_t)(512 + krow) * 512 + n0b + c4]);
        }
    }
    __syncthreads();

    float* Aw = As + (tid >> 5) * AW_WARP;    // this warp's staging area

    // phase1 maps (all warp-local)
    const int g1 = tid & 3, am = tid >> 2, amloc = (tid >> 2) & 7;
    const int rr1 = tid >> 3, cc1 = tid & 7, rr1loc = (tid >> 3) & 3;
    // phase2 maps (all warp-local)
    const int m2 = tid >> 3, m2loc = (tid >> 3) & 3;
    const int g2e = 2 * (tid & 3) + ((tid >> 2) & 1);
    const int rr2 = tid >> 4, cc2 = tid & 15, rr2loc = (tid >> 4) & 1;

    for (int t = 0; t < TT; t++) {
        if (t > 0) band_wait(&g_c2[(t - 1) * 4 + band], 32);

        // =================== Phase 1: h @ Wg_h (warp-independent) ==========
        {
            const int b0 = m0 + 2 * rr1, nn = n0 + 4 * cc1;
            const size_t gxo = ((size_t)t * BB + b0) * 1024 + nn;
            float4 gx0 = __ldg((const float4*)&g_gx[gxo]);
            float4 gx1 = __ldg((const float4*)&g_gx[gxo + 1024]);
            float4 h0, h1;
            if (is_rh) {
                h0 = __ldcg((const float4*)&g_h[(size_t)b0 * 512 + (nn - 512)]);
                h1 = __ldcg((const float4*)&g_h[(size_t)(b0 + 1) * 512 + (nn - 512)]);
            }

            const float* Ab = g_h + (size_t)(m0 + am) * 512 + 2 * g1;
            float2 pa[4], na[4];
#pragma unroll
            for (int j = 0; j < 4; j++) pa[j] = __ldcg((const float2*)(Ab + 8 * j));
#pragma unroll
            for (int j = 0; j < 4; j++) {   // stage kb0 into buf0 (warp-local)
                *(u64*)&Aw[(8 * j + 2 * g1) * AS_STRIDE + 2 * amloc]       = dup2(pa[j].x);
                *(u64*)&Aw[(8 * j + 2 * g1 + 1) * AS_STRIDE + 2 * amloc]   = dup2(pa[j].y);
            }
#pragma unroll
            for (int j = 0; j < 4; j++) na[j] = __ldcg((const float2*)(Ab + 32 + 8 * j));

            u64 a00 = 0, a01v = 0, a10 = 0, a11 = 0;
            for (int kb = 0; kb < 16; kb++) {
                __syncwarp();
                if (kb < 15) {
                    float* dst = Aw + ((kb + 1) & 1) * AW_BUF;
#pragma unroll
                    for (int j = 0; j < 4; j++) {
                        *(u64*)&dst[(8 * j + 2 * g1) * AS_STRIDE + 2 * amloc]     = dup2(na[j].x);
                        *(u64*)&dst[(8 * j + 2 * g1 + 1) * AS_STRIDE + 2 * amloc] = dup2(na[j].y);
                    }
                    if (kb < 14) {
                        const float* An = Ab + (kb + 2) * 32;
#pragma unroll
                        for (int j = 0; j < 4; j++) na[j] = __ldcg((const float2*)(An + 8 * j));
                    }
                }
                const float* Ak = Aw + (kb & 1) * AW_BUF;
                const float* Bk = B1s + kb * 1024;
#pragma unroll
                for (int k = 0; k < 32; k++) {
                    ulonglong2 a = *(const ulonglong2*)&Ak[k * AS_STRIDE + 4 * rr1loc];
                    ulonglong2 b = *(const ulonglong2*)&Bk[k * 32 + 4 * cc1];
                    fma2(a00, a.x, b.x); fma2(a01v, a.x, b.y);
                    fma2(a10, a.y, b.x); fma2(a11, a.y, b.y);
                }
            }

            float2 p00 = upk(a00), p01 = upk(a01v), p10 = upk(a10), p11 = upk(a11);
            float4 v0 = make_float4(sigm(p00.x + gx0.x), sigm(p00.y + gx0.y),
                                    sigm(p01.x + gx0.z), sigm(p01.y + gx0.w));
            float4 v1 = make_float4(sigm(p10.x + gx1.x), sigm(p10.y + gx1.y),
                                    sigm(p11.x + gx1.z), sigm(p11.y + gx1.w));
            if (!is_rh) {
                __stcg((float4*)&g_u[(size_t)b0 * 512 + nn], v0);
                __stcg((float4*)&g_u[(size_t)(b0 + 1) * 512 + nn], v1);
            } else {
                float4 r0 = make_float4(v0.x * h0.x, v0.y * h0.y, v0.z * h0.z, v0.w * h0.w);
                float4 r1 = make_float4(v1.x * h1.x, v1.y * h1.y, v1.z * h1.z, v1.w * h1.w);
                __stcg((float4*)&g_rh[(size_t)b0 * 512 + (nn - 512)], r0);
                __stcg((float4*)&g_rh[(size_t)(b0 + 1) * 512 + (nn - 512)], r1);
            }
        }
        band_arrive(is_rh ? &g_c1r[t * 4 + band] : &g_c1u[t * 4 + band]);
        band_wait(&g_c1r[t * 4 + band], 16);    // only rh half gates the GEMM

        // =================== Phase 2: rh @ Wh_h (warp-independent) =========
        {
            const int b0 = m0b + 2 * rr2, nn = n0b + 2 * cc2;
            const size_t cxo = ((size_t)t * BB + b0) * 512 + nn;
            float2 cx0 = __ldg((const float2*)&g_cx[cxo]);
            float2 cx1 = __ldg((const float2*)&g_cx[cxo + 512]);
            float2 h0 = __ldcg((const float2*)&g_h[(size_t)b0 * 512 + nn]);
            float2 h1 = __ldcg((const float2*)&g_h[(size_t)(b0 + 1) * 512 + nn]);

            const float* Ab2 = g_rh + (size_t)(m0b + m2) * 512 + g2e;
            float ra[4], nb[4];
#pragma unroll
            for (int j = 0; j < 4; j++) ra[j] = __ldcg(Ab2 + 8 * j);
#pragma unroll
            for (int j = 0; j < 4; j++)
                *(u64*)&Aw[(8 * j + g2e) * AS_STRIDE + 2 * m2loc] = dup2(ra[j]);
#pragma unroll
            for (int j = 0; j < 4; j++) nb[j] = __ldcg(Ab2 + 32 + 8 * j);

            u64 a0 = 0, a1 = 0;
            for (int kb = 0; kb < 16; kb++) {
                __syncwarp();
                if (kb < 15) {
                    float* dst = Aw + ((kb + 1) & 1) * AW_BUF;
#pragma unroll
                    for (int j = 0; j < 4; j++)
                        *(u64*)&dst[(8 * j + g2e) * AS_STRIDE + 2 * m2loc] = dup2(nb[j]);
                    if (kb < 14) {
#pragma unroll
                        for (int j = 0; j < 4; j++) nb[j] = __ldcg(Ab2 + (kb + 2) * 32 + 8 * j);
                    }
                }
                const float* Ak = Aw + (kb & 1) * AW_BUF;
                const float* Bk = B2s + kb * 1024;
#pragma unroll
                for (int k = 0; k < 32; k++) {
                    ulonglong2 a = *(const ulonglong2*)&Ak[k * AS_STRIDE + 4 * rr2loc];
                    u64 b = *(const u64*)&Bk[k * 32 + 2 * cc2];
                    fma2(a0, a.x, b); fma2(a1, a.y, b);
                }
            }

            band_wait(&g_c1u[t * 4 + band], 16);   // u ready (usually instant)
            float2 u0 = __ldcg((const float2*)&g_u[(size_t)b0 * 512 + nn]);
            float2 u1 = __ldcg((const float2*)&g_u[(size_t)(b0 + 1) * 512 + nn]);

            float2 p0 = upk(a0), p1 = upk(a1);
            float c00 = tanhf(p0.x + cx0.x), c01 = tanhf(p0.y + cx0.y);
            float c10 = tanhf(p1.x + cx1.x), c11 = tanhf(p1.y + cx1.y);
            float2 hn0 = make_float2(fmaf(u0.x, c00 - h0.x, h0.x), fmaf(u0.y, c01 - h0.y, h0.y));
            float2 hn1 = make_float2(fmaf(u1.x, c10 - h1.x, h1.x), fmaf(u1.y, c11 - h1.y, h1.y));
            __stcg((float2*)&g_h[(size_t)b0 * 512 + nn], hn0);
            __stcg((float2*)&g_h[(size_t)(b0 + 1) * 512 + nn], hn1);
            const size_t ho = ((size_t)t * BB + b0) * 512 + nn;
            *(float2*)&g_hist[ho] = hn0;
            *(float2*)&g_hist[ho + 512] = hn1;
        }
        band_arrive(&g_c2[t * 4 + band]);
    }
}

// ============================================================================
// k_y: output head off the critical path (unchanged).
// ============================================================================
__global__ __launch_bounds__(256) void k_y(
    const float* __restrict__ Wo1, const float* __restrict__ bo1,
    const float* __restrict__ Wo2, const float* __restrict__ bo2,
    float* __restrict__ out)
{
    __shared__ __align__(16) float Asd[32][68];
    __shared__ __align__(16) float Bs[32][256];

    const int tid = threadIdx.x;
    const long m0 = (long)blockIdx.x * 32;
    const int lk = tid & 31, lm = tid >> 5;
    const int rg = tid >> 5, cg = tid & 31;

    u64 acc[4][4];
#pragma unroll
    for (int r = 0; r < 4; r++)
#pragma unroll
        for (int p = 0; p < 4; p++) acc[r][p] = 0ull;

    for (int k0 = 0; k0 < HH; k0 += 32) {
        const float* ap = g_hist + m0 * HH + k0 + lk;
#pragma unroll
        for (int i = 0; i < 4; i++) {
            float v = ap[(long)(lm + 8 * i) * HH];
            *(u64*)&Asd[lk][2 * (lm + 8 * i)] = dup2(v);
        }
        const int bn = (tid & 63) * 4;
        const int bkk = tid >> 6;
#pragma unroll
        for (int j = 0; j < 8; j++) {
            float4 v = *(const float4*)&Wo1[(long)(k0 + bkk + 4 * j) * 256 + bn];
            *(float4*)&Bs[bkk + 4 * j][bn] = v;
        }
        __syncthreads();

#pragma unroll
        for (int k = 0; k < 32; k++) {
            ulonglong2 a01 = *(const ulonglong2*)&Asd[k][8 * rg];
            ulonglong2 a23 = *(const ulonglong2*)&Asd[k][8 * rg + 4];
            ulonglong2 b01 = *(const ulonglong2*)&Bs[k][8 * cg];
            ulonglong2 b23 = *(const ulonglong2*)&Bs[k][8 * cg + 4];
            fma2(acc[0][0], a01.x, b01.x); fma2(acc[0][1], a01.x, b01.y);
            fma2(acc[0][2], a01.x, b23.x); fma2(acc[0][3], a01.x, b23.y);
            fma2(acc[1][0], a01.y, b01.x); fma2(acc[1][1], a01.y, b01.y);
            fma2(acc[1][2], a01.y, b23.x); fma2(acc[1][3], a01.y, b23.y);
            fma2(acc[2][0], a23.x, b01.x); fma2(acc[2][1], a23.x, b01.y);
            fma2(acc[2][2], a23.x, b23.x); fma2(acc[2][3], a23.x, b23.y);
            fma2(acc[3][0], a23.y, b01.x); fma2(acc[3][1], a23.y, b01.y);
            fma2(acc[3][2], a23.y, b23.x); fma2(acc[3][3], a23.y, b23.y);
        }
        __syncthreads();
    }

    float b1[8], w2[8];
#pragma unroll
    for (int q = 0; q < 8; q++) { const int n = 8 * cg + q; b1[q] = bo1[n]; w2[q] = Wo2[n]; }
    const float bo2v = bo2[0];

#pragma unroll
    for (int r = 0; r < 4; r++) {
        float part = 0.f;
#pragma unroll
        for (int p = 0; p < 4; p++) {
            float2 z = upk(acc[r][p]);
            float z0 = fmaxf(z.x + b1[2 * p], 0.f);
            float z1 = fmaxf(z.y + b1[2 * p + 1], 0.f);
            part = fmaf(z0, w2[2 * p], part);
            part = fmaf(z1, w2[2 * p + 1], part);
        }
#pragma unroll
        for (int o = 16; o > 0; o >>= 1) part += __shfl_xor_sync(0xffffffffu, part, o);
        if (cg == 0) {
            const long m = m0 + 4 * rg + r;       // m = t*256 + b
            const int b = (int)(m & 255);
            const int tt = (int)(m >> 8);
            out[(long)b * TT + tt] = part + bo2v; // ys[b][t][0]
        }
    }
}

__global__ void k_init() {
    const int i = blockIdx.x * 256 + threadIdx.x;
    if (i < BB * HH) g_h[i] = 0.f;
    if (i < 4 * TT) { g_c1r[i] = 0u; g_c1u[i] = 0u; g_c2[i] = 0u; }
}

__global__ void k_hfinal(float* __restrict__ out) {
    const int i = blockIdx.x * 256 + threadIdx.x;
    out[(long)BB * TT + i] = g_h[i];
}

// ============================================================================
extern "C" void kernel_launch(void* const* d_in, const int* in_sizes, int n_in,
                              void* d_out, int out_size)
{
    (void)in_sizes; (void)n_in;
    const float* x   = (const float*)d_in[0];
    const float* Wg  = (const float*)d_in[1];
    const float* bg  = (const float*)d_in[2];
    const float* Wh  = (const float*)d_in[3];
    const float* bh  = (const float*)d_in[4];
    const float* Wo1 = (const float*)d_in[5];
    const float* bo1 = (const float*)d_in[6];
    const float* Wo2 = (const float*)d_in[7];
    const float* bo2 = (const float*)d_in[8];
    float* out = (float*)d_out;

    int dev = 0, nsm = 0;
    cudaGetDevice(&dev);
    cudaDeviceGetAttribute(&nsm, cudaDevAttrMultiProcessorCount, dev);
    int nCTA = (nsm >= 128) ? nsm : 128;   // extras exit immediately

    cudaFuncSetAttribute(k_persist, cudaFuncAttributeMaxDynamicSharedMemorySize,
                         SMEM_FLOATS * (int)sizeof(float));

    k_init<<<512, 256>>>();
    k_pre<<<2048 * 24, 256>>>(x, Wg, bg, Wh, bh);
    k_persist<<<nCTA, 256, SMEM_FLOATS * sizeof(float)>>>(Wg, Wh);
    k_y<<<(BB * TT) / 32, 256>>>(Wo1, bo1, Wo2, bo2, out);

    if (out_size >= BB * TT + BB * HH)
        k_hfinal<<<(BB * HH) / 256, 256>>>(out);
}